// round 1
// baseline (speedup 1.0000x reference)
#include <cuda_runtime.h>
#include <math.h>

#define D_MODEL 1024
#define QKV_F   3072
#define NHEADS  16
#define HDIM    64
#define BATCH   4
#define SEQ     2048

// Scratch (allocation-free rule: __device__ globals)
__device__ float g_qkv[(size_t)BATCH * SEQ * QKV_F];   // [B,T,3C]
__device__ float g_y  [(size_t)BATCH * SEQ * D_MODEL]; // [B,T,C]  (heads re-merged)

// ---------------------------------------------------------------------------
// C[M,N] = A[M,K] @ W[N,K]^T      (torch Linear layout: W is [out, in])
// 128x128 block tile, BK=8, 256 threads, 8x8 per-thread microtile.
// ---------------------------------------------------------------------------
__global__ __launch_bounds__(256, 2)
void sgemm_nt(const float* __restrict__ A, const float* __restrict__ W,
              float* __restrict__ C, int M, int N, int K)
{
    __shared__ float As[8][128];
    __shared__ float Bs[8][128];

    const int tid = threadIdx.x;
    const float* Ap = A + (size_t)blockIdx.y * 128 * K;
    const float* Wp = W + (size_t)blockIdx.x * 128 * K;

    const int ldRow = tid >> 1;          // 0..127
    const int ldCol = (tid & 1) << 2;    // 0 or 4
    const int tRow  = (tid >> 4) << 3;   // 0..120 step 8
    const int tCol  = (tid & 15) << 3;   // 0..120 step 8

    float acc[8][8];
#pragma unroll
    for (int i = 0; i < 8; i++)
#pragma unroll
        for (int j = 0; j < 8; j++) acc[i][j] = 0.f;

    for (int k0 = 0; k0 < K; k0 += 8) {
        float4 av = *(const float4*)(Ap + (size_t)ldRow * K + k0 + ldCol);
        float4 bv = *(const float4*)(Wp + (size_t)ldRow * K + k0 + ldCol);
        As[ldCol + 0][ldRow] = av.x; As[ldCol + 1][ldRow] = av.y;
        As[ldCol + 2][ldRow] = av.z; As[ldCol + 3][ldRow] = av.w;
        Bs[ldCol + 0][ldRow] = bv.x; Bs[ldCol + 1][ldRow] = bv.y;
        Bs[ldCol + 2][ldRow] = bv.z; Bs[ldCol + 3][ldRow] = bv.w;
        __syncthreads();

#pragma unroll
        for (int kk = 0; kk < 8; kk++) {
            float ra[8], rb[8];
            *(float4*)&ra[0] = *(const float4*)&As[kk][tRow];
            *(float4*)&ra[4] = *(const float4*)&As[kk][tRow + 4];
            *(float4*)&rb[0] = *(const float4*)&Bs[kk][tCol];
            *(float4*)&rb[4] = *(const float4*)&Bs[kk][tCol + 4];
#pragma unroll
            for (int i = 0; i < 8; i++)
#pragma unroll
                for (int j = 0; j < 8; j++)
                    acc[i][j] += ra[i] * rb[j];
        }
        __syncthreads();
    }

    float* Cp = C + (size_t)blockIdx.y * 128 * N + blockIdx.x * 128;
#pragma unroll
    for (int i = 0; i < 8; i++) {
        *(float4*)(Cp + (size_t)(tRow + i) * N + tCol)     = *(float4*)&acc[i][0];
        *(float4*)(Cp + (size_t)(tRow + i) * N + tCol + 4) = *(float4*)&acc[i][4];
    }
}

// ---------------------------------------------------------------------------
// Flash attention, causal. 64x64 q/k tiles, Dh=64. Block = 256 threads as
// 16(ty: row groups of 4) x 16(tx: col groups of 4). Online softmax state
// replicated across the 16 threads of each half-warp row group via shfl.
// ---------------------------------------------------------------------------
#define BQ   64
#define STRD 68   // 16B-aligned padded row stride (words)

__global__ __launch_bounds__(256)
void attn_kernel()
{
    extern __shared__ float sm[];
    float* Qs  = sm;                  // [64][STRD]  row-major [q][d]
    float* Kst = Qs  + BQ * STRD;     // [64][STRD]  TRANSPOSED: [d][k]
    float* Vs  = Kst + BQ * STRD;     // [64][STRD]  row-major [k][d]
    float* Ps  = Vs  + BQ * STRD;     // [64][STRD]  probs [q][k]

    const int tid = threadIdx.x;
    const int ty  = tid >> 4;   // 0..15 -> q rows ty*4..ty*4+3
    const int tx  = tid & 15;   // 0..15 -> cols tx*4..tx*4+3
    const int qt  = gridDim.x - 1 - blockIdx.x;   // heavy tiles first
    const int h   = blockIdx.y;
    const int b   = blockIdx.z;
    const int q0  = qt * BQ;

    // loader mapping: row lr (0..63), 16 consecutive cols at lc
    const int lr = tid >> 2;
    const int lc = (tid & 3) << 4;

    // Load Q tile once
    {
        const float* src = g_qkv + ((size_t)(b * SEQ + q0 + lr) * QKV_F) + h * HDIM + lc;
        float* dst = Qs + lr * STRD + lc;
#pragma unroll
        for (int j = 0; j < 16; j += 4) {
            float4 v = *(const float4*)(src + j);
            dst[j] = v.x; dst[j + 1] = v.y; dst[j + 2] = v.z; dst[j + 3] = v.w;
        }
    }

    float m[4], l[4], o[4][4];
#pragma unroll
    for (int i = 0; i < 4; i++) {
        m[i] = -1e30f; l[i] = 0.f;
#pragma unroll
        for (int j = 0; j < 4; j++) o[i][j] = 0.f;
    }

    const float scale = 0.125f;   // 1/sqrt(64)

    for (int kt = 0; kt <= qt; kt++) {
        __syncthreads();   // protect K/V/P smem vs previous iteration (and Q load)
        const int kk0 = kt * BQ;
        {
            const float* ksrc = g_qkv + ((size_t)(b * SEQ + kk0 + lr) * QKV_F)
                                + D_MODEL + h * HDIM + lc;
            const float* vsrc = ksrc + D_MODEL;
            float* vd = Vs + lr * STRD + lc;
#pragma unroll
            for (int j = 0; j < 16; j += 4) {
                float4 kv = *(const float4*)(ksrc + j);
                Kst[(lc + j + 0) * STRD + lr] = kv.x;   // transpose K: [d][k]
                Kst[(lc + j + 1) * STRD + lr] = kv.y;
                Kst[(lc + j + 2) * STRD + lr] = kv.z;
                Kst[(lc + j + 3) * STRD + lr] = kv.w;
                float4 vv = *(const float4*)(vsrc + j);
                vd[j] = vv.x; vd[j + 1] = vv.y; vd[j + 2] = vv.z; vd[j + 3] = vv.w;
            }
        }
        __syncthreads();

        // S = Q K^T (4x4 microtile)
        float s[4][4];
#pragma unroll
        for (int i = 0; i < 4; i++)
#pragma unroll
            for (int j = 0; j < 4; j++) s[i][j] = 0.f;

        for (int d = 0; d < HDIM; d++) {
            float ra[4], rb[4];
#pragma unroll
            for (int i = 0; i < 4; i++) ra[i] = Qs[(ty * 4 + i) * STRD + d];
            *(float4*)&rb[0] = *(const float4*)&Kst[d * STRD + tx * 4];
#pragma unroll
            for (int i = 0; i < 4; i++)
#pragma unroll
                for (int j = 0; j < 4; j++)
                    s[i][j] += ra[i] * rb[j];
        }

        // scale + causal mask
#pragma unroll
        for (int i = 0; i < 4; i++) {
            const int qrow = q0 + ty * 4 + i;
#pragma unroll
            for (int j = 0; j < 4; j++) {
                const int kcol = kk0 + tx * 4 + j;
                s[i][j] = (kcol <= qrow) ? s[i][j] * scale : -1e30f;
            }
        }

        // online softmax (row state across 16-lane half-warp group)
        float alpha[4];
#pragma unroll
        for (int i = 0; i < 4; i++) {
            float mx = fmaxf(fmaxf(s[i][0], s[i][1]), fmaxf(s[i][2], s[i][3]));
#pragma unroll
            for (int off = 1; off < 16; off <<= 1)
                mx = fmaxf(mx, __shfl_xor_sync(0xffffffffu, mx, off));
            float mnew = fmaxf(m[i], mx);
            alpha[i] = __expf(m[i] - mnew);
            m[i] = mnew;
        }

#pragma unroll
        for (int i = 0; i < 4; i++) {
            float rs = 0.f;
#pragma unroll
            for (int j = 0; j < 4; j++) {
                float p = __expf(s[i][j] - m[i]);
                s[i][j] = p;
                rs += p;
            }
#pragma unroll
            for (int off = 1; off < 16; off <<= 1)
                rs += __shfl_xor_sync(0xffffffffu, rs, off);
            l[i] = l[i] * alpha[i] + rs;
#pragma unroll
            for (int j = 0; j < 4; j++) o[i][j] *= alpha[i];
            *(float4*)&Ps[(ty * 4 + i) * STRD + tx * 4] = *(float4*)&s[i][0];
        }
        __syncthreads();

        // O += P @ V   (thread owns q rows ty*4.., d cols tx*4..)
        for (int c = 0; c < BQ; c++) {
            float pa[4], vb[4];
#pragma unroll
            for (int i = 0; i < 4; i++) pa[i] = Ps[(ty * 4 + i) * STRD + c];
            *(float4*)&vb[0] = *(const float4*)&Vs[c * STRD + tx * 4];
#pragma unroll
            for (int i = 0; i < 4; i++)
#pragma unroll
                for (int j = 0; j < 4; j++)
                    o[i][j] += pa[i] * vb[j];
        }
    }

    // normalize + write y[b, q0+row, h*64 + col]  (heads re-merged layout)
#pragma unroll
    for (int i = 0; i < 4; i++) {
        float inv = 1.f / l[i];
        float4 v;
        v.x = o[i][0] * inv; v.y = o[i][1] * inv;
        v.z = o[i][2] * inv; v.w = o[i][3] * inv;
        *(float4*)(g_y + ((size_t)(b * SEQ + q0 + ty * 4 + i) * D_MODEL)
                   + h * HDIM + tx * 4) = v;
    }
}

static const size_t ATTN_SMEM = (size_t)4 * BQ * STRD * sizeof(float);  // 69632 B

extern "C" void kernel_launch(void* const* d_in, const int* in_sizes, int n_in,
                              void* d_out, int out_size)
{
    (void)in_sizes; (void)n_in; (void)out_size;
    const float* x      = (const float*)d_in[0];
    const float* w_qkv  = (const float*)d_in[1];
    const float* w_proj = (const float*)d_in[2];
    float* out = (float*)d_out;

    float* qkv = nullptr;
    float* y   = nullptr;
    cudaGetSymbolAddress((void**)&qkv, g_qkv);
    cudaGetSymbolAddress((void**)&y,   g_y);

    const int M = BATCH * SEQ;  // 8192

    // 1) qkv = x @ w_qkv^T
    sgemm_nt<<<dim3(QKV_F / 128, M / 128), 256>>>(x, w_qkv, qkv, M, QKV_F, D_MODEL);

    // 2) flash attention (causal) -> y (heads merged)
    cudaFuncSetAttribute(attn_kernel,
                         cudaFuncAttributeMaxDynamicSharedMemorySize, (int)ATTN_SMEM);
    attn_kernel<<<dim3(SEQ / BQ, NHEADS, BATCH), 256, ATTN_SMEM>>>();

    // 3) out = y @ w_proj^T
    sgemm_nt<<<dim3(D_MODEL / 128, M / 128), 256>>>(y, w_proj, out, M, D_MODEL, D_MODEL);
}

// round 3
// speedup vs baseline: 1.5295x; 1.5295x over previous
#include <cuda_runtime.h>
#include <cuda_bf16.h>
#include <cstdint>
#include <math.h>

#define D_MODEL 1024
#define QKV_F   3072
#define NHEADS  16
#define HDIM    64
#define BATCH   4
#define SEQ     2048
#define MROWS   (BATCH * SEQ)   // 8192

// ---------------------------------------------------------------------------
// Scratch (__device__ globals; allocation-free rule)
// ---------------------------------------------------------------------------
__device__ float g_qkv[(size_t)MROWS * QKV_F];      // [B*T, 3C] fp32
__device__ float g_y  [(size_t)MROWS * D_MODEL];    // [B*T, C]  fp32
__device__ __nv_bfloat16 g_x_hi[(size_t)MROWS * D_MODEL];
__device__ __nv_bfloat16 g_x_lo[(size_t)MROWS * D_MODEL];
__device__ __nv_bfloat16 g_y_hi[(size_t)MROWS * D_MODEL];
__device__ __nv_bfloat16 g_y_lo[(size_t)MROWS * D_MODEL];
__device__ __nv_bfloat16 g_wqkv_hi[(size_t)QKV_F * D_MODEL];
__device__ __nv_bfloat16 g_wqkv_lo[(size_t)QKV_F * D_MODEL];
__device__ __nv_bfloat16 g_wproj_hi[(size_t)D_MODEL * D_MODEL];
__device__ __nv_bfloat16 g_wproj_lo[(size_t)D_MODEL * D_MODEL];

// ---------------------------------------------------------------------------
// Helpers (base sm_103 ISA only: mma.sync / ldmatrix / cp.async)
// ---------------------------------------------------------------------------
__device__ __forceinline__ uint32_t smem_u32(const void* p) {
    uint32_t a;
    asm("{ .reg .u64 t; cvta.to.shared.u64 t, %1; cvt.u32.u64 %0, t; }" : "=r"(a) : "l"(p));
    return a;
}
__device__ __forceinline__ void ldsm_x4(uint32_t* r, uint32_t addr) {
    asm volatile("ldmatrix.sync.aligned.m8n8.x4.shared.b16 {%0,%1,%2,%3}, [%4];"
        : "=r"(r[0]), "=r"(r[1]), "=r"(r[2]), "=r"(r[3]) : "r"(addr));
}
__device__ __forceinline__ void mma16816(float* d, const uint32_t* a, const uint32_t* b) {
    asm volatile("mma.sync.aligned.m16n8k16.row.col.f32.bf16.bf16.f32 "
        "{%0,%1,%2,%3}, {%4,%5,%6,%7}, {%8,%9}, {%0,%1,%2,%3};"
        : "+f"(d[0]), "+f"(d[1]), "+f"(d[2]), "+f"(d[3])
        : "r"(a[0]), "r"(a[1]), "r"(a[2]), "r"(a[3]), "r"(b[0]), "r"(b[1]));
}
#define CP_ASYNC16(dst, src) \
    asm volatile("cp.async.cg.shared.global [%0], [%1], 16;" :: "r"(dst), "l"(src) : "memory")
#define CP_COMMIT() asm volatile("cp.async.commit_group;" ::: "memory")

// ---------------------------------------------------------------------------
// fp32 -> (bf16 hi, bf16 lo) split
// ---------------------------------------------------------------------------
__global__ void split_bf16_kernel(const float* __restrict__ in,
                                  __nv_bfloat16* __restrict__ hi,
                                  __nv_bfloat16* __restrict__ lo, int n4)
{
    int i = blockIdx.x * blockDim.x + threadIdx.x;
    if (i >= n4) return;
    float4 v = ((const float4*)in)[i];
    __nv_bfloat16 h0 = __float2bfloat16(v.x);
    __nv_bfloat16 h1 = __float2bfloat16(v.y);
    __nv_bfloat16 h2 = __float2bfloat16(v.z);
    __nv_bfloat16 h3 = __float2bfloat16(v.w);
    __nv_bfloat16 l0 = __float2bfloat16(v.x - __bfloat162float(h0));
    __nv_bfloat16 l1 = __float2bfloat16(v.y - __bfloat162float(h1));
    __nv_bfloat16 l2 = __float2bfloat16(v.z - __bfloat162float(h2));
    __nv_bfloat16 l3 = __float2bfloat16(v.w - __bfloat162float(h3));
    __nv_bfloat162* hp = (__nv_bfloat162*)(hi + (size_t)i * 4);
    __nv_bfloat162* lp = (__nv_bfloat162*)(lo + (size_t)i * 4);
    hp[0] = __nv_bfloat162(h0, h1); hp[1] = __nv_bfloat162(h2, h3);
    lp[0] = __nv_bfloat162(l0, l1); lp[1] = __nv_bfloat162(l2, l3);
}

// ---------------------------------------------------------------------------
// mma.sync GEMM: C[M,N] = A[M,K] @ W[N,K]^T  (bf16x3 split, fp32 accum)
// CTA 128x128, BK=32, 256 threads (8 warps, 2m x 4n), warp tile 64x32.
// Smem per operand plane: [128][32] bf16, 16B-chunk swizzle c ^ ((row>>1)&3).
// ---------------------------------------------------------------------------
#define BM 128
#define BN 128
#define BK 32
#define TILEB  (BM * BK * 2)     // 8192 B per plane
#define STAGEB (4 * TILEB)       // Ahi,Alo,Whi,Wlo = 32 KB
#define GEMM_SMEM (2 * STAGEB)   // 64 KB

__global__ __launch_bounds__(256, 1)
void gemm_mma(const __nv_bfloat16* __restrict__ Ahi, const __nv_bfloat16* __restrict__ Alo,
              const __nv_bfloat16* __restrict__ Whi, const __nv_bfloat16* __restrict__ Wlo,
              float* __restrict__ C, int N, int K)
{
    extern __shared__ char smem[];
    const uint32_t sbase = smem_u32(smem);
    const int tid  = threadIdx.x;
    const int wid  = tid >> 5;
    const int lane = tid & 31;
    const int wm   = wid & 1;        // 0..1  (64 rows each)
    const int wn   = wid >> 1;       // 0..3  (32 cols each)
    const int m0   = blockIdx.y * BM;
    const int n0   = blockIdx.x * BN;

    // loader mapping: 256 threads; row = tid>>1 (0..127), chunks (tid&1)*2 + {0,1}
    const int lrow = tid >> 1;
    const int lc0  = (tid & 1) * 2;
    const int lswz = (lrow >> 1) & 3;

    const __nv_bfloat16* srcs[4];
    srcs[0] = Ahi + (size_t)(m0 + lrow) * K;
    srcs[1] = Alo + (size_t)(m0 + lrow) * K;
    srcs[2] = Whi + (size_t)(n0 + lrow) * K;
    srcs[3] = Wlo + (size_t)(n0 + lrow) * K;

    auto LOAD = [&](int s, int c) {
#pragma unroll
        for (int a = 0; a < 4; a++) {
#pragma unroll
            for (int j = 0; j < 2; j++) {
                const int cl = lc0 + j;
                const uint32_t dst = sbase + s * STAGEB + a * TILEB
                                   + lrow * 64 + ((cl ^ lswz) << 4);
                CP_ASYNC16(dst, srcs[a] + (size_t)c * BK + cl * 8);
            }
        }
    };

    float acc[4][4][4];
#pragma unroll
    for (int i = 0; i < 4; i++)
#pragma unroll
        for (int j = 0; j < 4; j++)
#pragma unroll
            for (int k = 0; k < 4; k++) acc[i][j][k] = 0.f;

    const int NC = K / BK;
    LOAD(0, 0);
    CP_COMMIT();

    // ldmatrix lane addressing precompute
    const int mi     = lane >> 3;     // matrix index 0..3
    const int row_in = lane & 7;
    // A: mat0 rows+0/klow, mat1 rows+8/klow, mat2 rows+0/khigh, mat3 rows+8/khigh
    const int a_rowadd = (mi & 1) * 8;
    const int a_cadd   = mi >> 1;
    // B: mat0 nt rows/klow, mat1 nt rows/khigh, mat2 nt+1 rows/klow, mat3 nt+1/khigh
    const int b_rowadd = (mi >> 1) * 8;
    const int b_cadd   = mi & 1;

    for (int c = 0; c < NC; c++) {
        const int s = c & 1;
        if (c + 1 < NC) {
            LOAD(s ^ 1, c + 1);
            CP_COMMIT();
            asm volatile("cp.async.wait_group 1;" ::: "memory");
        } else {
            asm volatile("cp.async.wait_group 0;" ::: "memory");
        }
        __syncthreads();

        const uint32_t st = sbase + s * STAGEB;
#pragma unroll
        for (int ks = 0; ks < 2; ks++) {
            uint32_t ah[4][4], al[4][4], bh[8], bl[8];
#pragma unroll
            for (int mt = 0; mt < 4; mt++) {
                const int r  = wm * 64 + mt * 16 + a_rowadd + row_in;
                const int cl = ks * 2 + a_cadd;
                const uint32_t off = r * 64 + ((cl ^ ((r >> 1) & 3)) << 4);
                ldsm_x4(ah[mt], st + 0 * TILEB + off);
                ldsm_x4(al[mt], st + 1 * TILEB + off);
            }
#pragma unroll
            for (int p = 0; p < 2; p++) {
                const int r  = wn * 32 + p * 16 + b_rowadd + row_in;
                const int cl = ks * 2 + b_cadd;
                const uint32_t off = r * 64 + ((cl ^ ((r >> 1) & 3)) << 4);
                ldsm_x4(&bh[p * 4], st + 2 * TILEB + off);
                ldsm_x4(&bl[p * 4], st + 3 * TILEB + off);
            }
#pragma unroll
            for (int mt = 0; mt < 4; mt++)
#pragma unroll
                for (int nt = 0; nt < 4; nt++) {
                    mma16816(acc[mt][nt], ah[mt], &bh[nt * 2]);
                    mma16816(acc[mt][nt], ah[mt], &bl[nt * 2]);
                    mma16816(acc[mt][nt], al[mt], &bh[nt * 2]);
                }
        }
        __syncthreads();
    }

    // epilogue: thread holds (row=lane>>2, col=(lane&3)*2) and row+8
#pragma unroll
    for (int mt = 0; mt < 4; mt++) {
#pragma unroll
        for (int nt = 0; nt < 4; nt++) {
            const int row = m0 + wm * 64 + mt * 16 + (lane >> 2);
            const int col = n0 + wn * 32 + nt * 8 + (lane & 3) * 2;
            *(float2*)(C + (size_t)row * N + col) =
                make_float2(acc[mt][nt][0], acc[mt][nt][1]);
            *(float2*)(C + (size_t)(row + 8) * N + col) =
                make_float2(acc[mt][nt][2], acc[mt][nt][3]);
        }
    }
}

// ---------------------------------------------------------------------------
// Flash attention (unchanged, known-good from round 1)
// ---------------------------------------------------------------------------
#define BQ   64
#define STRD 68

__global__ __launch_bounds__(256)
void attn_kernel()
{
    extern __shared__ float sm[];
    float* Qs  = sm;
    float* Kst = Qs  + BQ * STRD;
    float* Vs  = Kst + BQ * STRD;
    float* Ps  = Vs  + BQ * STRD;

    const int tid = threadIdx.x;
    const int ty  = tid >> 4;
    const int tx  = tid & 15;
    const int qt  = gridDim.x - 1 - blockIdx.x;
    const int h   = blockIdx.y;
    const int b   = blockIdx.z;
    const int q0  = qt * BQ;

    const int lr = tid >> 2;
    const int lc = (tid & 3) << 4;

    {
        const float* src = g_qkv + ((size_t)(b * SEQ + q0 + lr) * QKV_F) + h * HDIM + lc;
        float* dst = Qs + lr * STRD + lc;
#pragma unroll
        for (int j = 0; j < 16; j += 4) {
            float4 v = *(const float4*)(src + j);
            dst[j] = v.x; dst[j + 1] = v.y; dst[j + 2] = v.z; dst[j + 3] = v.w;
        }
    }

    float m[4], l[4], o[4][4];
#pragma unroll
    for (int i = 0; i < 4; i++) {
        m[i] = -1e30f; l[i] = 0.f;
#pragma unroll
        for (int j = 0; j < 4; j++) o[i][j] = 0.f;
    }
    const float scale = 0.125f;

    for (int kt = 0; kt <= qt; kt++) {
        __syncthreads();
        const int kk0 = kt * BQ;
        {
            const float* ksrc = g_qkv + ((size_t)(b * SEQ + kk0 + lr) * QKV_F)
                                + D_MODEL + h * HDIM + lc;
            const float* vsrc = ksrc + D_MODEL;
            float* vd = Vs + lr * STRD + lc;
#pragma unroll
            for (int j = 0; j < 16; j += 4) {
                float4 kv = *(const float4*)(ksrc + j);
                Kst[(lc + j + 0) * STRD + lr] = kv.x;
                Kst[(lc + j + 1) * STRD + lr] = kv.y;
                Kst[(lc + j + 2) * STRD + lr] = kv.z;
                Kst[(lc + j + 3) * STRD + lr] = kv.w;
                float4 vv = *(const float4*)(vsrc + j);
                vd[j] = vv.x; vd[j + 1] = vv.y; vd[j + 2] = vv.z; vd[j + 3] = vv.w;
            }
        }
        __syncthreads();

        float s[4][4];
#pragma unroll
        for (int i = 0; i < 4; i++)
#pragma unroll
            for (int j = 0; j < 4; j++) s[i][j] = 0.f;

        for (int d = 0; d < HDIM; d++) {
            float ra[4], rb[4];
#pragma unroll
            for (int i = 0; i < 4; i++) ra[i] = Qs[(ty * 4 + i) * STRD + d];
            *(float4*)&rb[0] = *(const float4*)&Kst[d * STRD + tx * 4];
#pragma unroll
            for (int i = 0; i < 4; i++)
#pragma unroll
                for (int j = 0; j < 4; j++)
                    s[i][j] += ra[i] * rb[j];
        }

#pragma unroll
        for (int i = 0; i < 4; i++) {
            const int qrow = q0 + ty * 4 + i;
#pragma unroll
            for (int j = 0; j < 4; j++) {
                const int kcol = kk0 + tx * 4 + j;
                s[i][j] = (kcol <= qrow) ? s[i][j] * scale : -1e30f;
            }
        }

        float alpha[4];
#pragma unroll
        for (int i = 0; i < 4; i++) {
            float mx = fmaxf(fmaxf(s[i][0], s[i][1]), fmaxf(s[i][2], s[i][3]));
#pragma unroll
            for (int off = 1; off < 16; off <<= 1)
                mx = fmaxf(mx, __shfl_xor_sync(0xffffffffu, mx, off));
            float mnew = fmaxf(m[i], mx);
            alpha[i] = __expf(m[i] - mnew);
            m[i] = mnew;
        }

#pragma unroll
        for (int i = 0; i < 4; i++) {
            float rs = 0.f;
#pragma unroll
            for (int j = 0; j < 4; j++) {
                float p = __expf(s[i][j] - m[i]);
                s[i][j] = p;
                rs += p;
            }
#pragma unroll
            for (int off = 1; off < 16; off <<= 1)
                rs += __shfl_xor_sync(0xffffffffu, rs, off);
            l[i] = l[i] * alpha[i] + rs;
#pragma unroll
            for (int j = 0; j < 4; j++) o[i][j] *= alpha[i];
            *(float4*)&Ps[(ty * 4 + i) * STRD + tx * 4] = *(float4*)&s[i][0];
        }
        __syncthreads();

        for (int c = 0; c < BQ; c++) {
            float pa[4], vb[4];
#pragma unroll
            for (int i = 0; i < 4; i++) pa[i] = Ps[(ty * 4 + i) * STRD + c];
            *(float4*)&vb[0] = *(const float4*)&Vs[c * STRD + tx * 4];
#pragma unroll
            for (int i = 0; i < 4; i++)
#pragma unroll
                for (int j = 0; j < 4; j++)
                    o[i][j] += pa[i] * vb[j];
        }
    }

#pragma unroll
    for (int i = 0; i < 4; i++) {
        float inv = 1.f / l[i];
        float4 v;
        v.x = o[i][0] * inv; v.y = o[i][1] * inv;
        v.z = o[i][2] * inv; v.w = o[i][3] * inv;
        *(float4*)(g_y + ((size_t)(b * SEQ + q0 + ty * 4 + i) * D_MODEL)
                   + h * HDIM + tx * 4) = v;
    }
}

static const size_t ATTN_SMEM = (size_t)4 * BQ * STRD * sizeof(float);

// ---------------------------------------------------------------------------
extern "C" void kernel_launch(void* const* d_in, const int* in_sizes, int n_in,
                              void* d_out, int out_size)
{
    (void)in_sizes; (void)n_in; (void)out_size;
    const float* x      = (const float*)d_in[0];
    const float* w_qkv  = (const float*)d_in[1];
    const float* w_proj = (const float*)d_in[2];
    float* out = (float*)d_out;

    float *qkv, *y;
    __nv_bfloat16 *xhi, *xlo, *yhi, *ylo, *wqh, *wql, *wph, *wpl;
    cudaGetSymbolAddress((void**)&qkv, g_qkv);
    cudaGetSymbolAddress((void**)&y,   g_y);
    cudaGetSymbolAddress((void**)&xhi, g_x_hi);
    cudaGetSymbolAddress((void**)&xlo, g_x_lo);
    cudaGetSymbolAddress((void**)&yhi, g_y_hi);
    cudaGetSymbolAddress((void**)&ylo, g_y_lo);
    cudaGetSymbolAddress((void**)&wqh, g_wqkv_hi);
    cudaGetSymbolAddress((void**)&wql, g_wqkv_lo);
    cudaGetSymbolAddress((void**)&wph, g_wproj_hi);
    cudaGetSymbolAddress((void**)&wpl, g_wproj_lo);

    cudaFuncSetAttribute(gemm_mma, cudaFuncAttributeMaxDynamicSharedMemorySize, GEMM_SMEM);
    cudaFuncSetAttribute(attn_kernel, cudaFuncAttributeMaxDynamicSharedMemorySize, (int)ATTN_SMEM);

    const int nX  = MROWS * D_MODEL / 4;
    const int nWq = QKV_F * D_MODEL / 4;
    const int nWp = D_MODEL * D_MODEL / 4;

    split_bf16_kernel<<<(nX + 255) / 256, 256>>>(x, xhi, xlo, nX);
    split_bf16_kernel<<<(nWq + 255) / 256, 256>>>(w_qkv, wqh, wql, nWq);
    split_bf16_kernel<<<(nWp + 255) / 256, 256>>>(w_proj, wph, wpl, nWp);

    gemm_mma<<<dim3(QKV_F / BN, MROWS / BM), 256, GEMM_SMEM>>>(
        xhi, xlo, wqh, wql, qkv, QKV_F, D_MODEL);

    attn_kernel<<<dim3(SEQ / BQ, NHEADS, BATCH), 256, ATTN_SMEM>>>();

    split_bf16_kernel<<<(nX + 255) / 256, 256>>>(y, yhi, ylo, nX);

    gemm_mma<<<dim3(D_MODEL / BN, MROWS / BM), 256, GEMM_SMEM>>>(
        yhi, ylo, wph, wpl, out, D_MODEL, D_MODEL);
}

// round 4
// speedup vs baseline: 1.6776x; 1.0968x over previous
#include <cuda_runtime.h>
#include <cuda_bf16.h>
#include <cstdint>
#include <math.h>

#define D_MODEL 1024
#define QKV_F   3072
#define NHEADS  16
#define HDIM    64
#define BATCH   4
#define SEQ     2048
#define MROWS   (BATCH * SEQ)   // 8192

// ---------------------------------------------------------------------------
// Scratch (__device__ globals; allocation-free rule)
// ---------------------------------------------------------------------------
__device__ __nv_bfloat16 g_qkv_hi[(size_t)MROWS * QKV_F];
__device__ __nv_bfloat16 g_qkv_lo[(size_t)MROWS * QKV_F];
__device__ __nv_bfloat16 g_x_hi[(size_t)MROWS * D_MODEL];
__device__ __nv_bfloat16 g_x_lo[(size_t)MROWS * D_MODEL];
__device__ __nv_bfloat16 g_y_hi[(size_t)MROWS * D_MODEL];
__device__ __nv_bfloat16 g_y_lo[(size_t)MROWS * D_MODEL];
__device__ __nv_bfloat16 g_wqkv_hi[(size_t)QKV_F * D_MODEL];
__device__ __nv_bfloat16 g_wqkv_lo[(size_t)QKV_F * D_MODEL];
__device__ __nv_bfloat16 g_wproj_hi[(size_t)D_MODEL * D_MODEL];
__device__ __nv_bfloat16 g_wproj_lo[(size_t)D_MODEL * D_MODEL];

// ---------------------------------------------------------------------------
// Helpers (base sm_103 ISA: mma.sync / ldmatrix / cp.async)
// ---------------------------------------------------------------------------
__device__ __forceinline__ uint32_t smem_u32(const void* p) {
    uint32_t a;
    asm("{ .reg .u64 t; cvta.to.shared.u64 t, %1; cvt.u32.u64 %0, t; }" : "=r"(a) : "l"(p));
    return a;
}
__device__ __forceinline__ void ldsm_x4(uint32_t* r, uint32_t addr) {
    asm volatile("ldmatrix.sync.aligned.m8n8.x4.shared.b16 {%0,%1,%2,%3}, [%4];"
        : "=r"(r[0]), "=r"(r[1]), "=r"(r[2]), "=r"(r[3]) : "r"(addr));
}
__device__ __forceinline__ void ldsm_x4_t(uint32_t* r, uint32_t addr) {
    asm volatile("ldmatrix.sync.aligned.m8n8.x4.trans.shared.b16 {%0,%1,%2,%3}, [%4];"
        : "=r"(r[0]), "=r"(r[1]), "=r"(r[2]), "=r"(r[3]) : "r"(addr));
}
__device__ __forceinline__ void mma16816(float* d, const uint32_t* a, const uint32_t* b) {
    asm volatile("mma.sync.aligned.m16n8k16.row.col.f32.bf16.bf16.f32 "
        "{%0,%1,%2,%3}, {%4,%5,%6,%7}, {%8,%9}, {%0,%1,%2,%3};"
        : "+f"(d[0]), "+f"(d[1]), "+f"(d[2]), "+f"(d[3])
        : "r"(a[0]), "r"(a[1]), "r"(a[2]), "r"(a[3]), "r"(b[0]), "r"(b[1]));
}
#define CP_ASYNC16(dst, src) \
    asm volatile("cp.async.cg.shared.global [%0], [%1], 16;" :: "r"(dst), "l"(src) : "memory")
#define CP_COMMIT() asm volatile("cp.async.commit_group;" ::: "memory")

__device__ __forceinline__ float ex2(float x) {
    float y; asm("ex2.approx.f32 %0, %1;" : "=f"(y) : "f"(x)); return y;
}
// split x0,x1 into packed bf16x2 hi & lo planes (x0 in low half)
__device__ __forceinline__ void split_pack2(float x0, float x1, uint32_t& hi, uint32_t& lo) {
    __nv_bfloat16 h0 = __float2bfloat16(x0), h1 = __float2bfloat16(x1);
    __nv_bfloat16 l0 = __float2bfloat16(x0 - __bfloat162float(h0));
    __nv_bfloat16 l1 = __float2bfloat16(x1 - __bfloat162float(h1));
    __nv_bfloat162 H(h0, h1), L(l0, l1);
    hi = *reinterpret_cast<uint32_t*>(&H);
    lo = *reinterpret_cast<uint32_t*>(&L);
}

// ---------------------------------------------------------------------------
// fp32 -> (bf16 hi, bf16 lo) elementwise split
// ---------------------------------------------------------------------------
__global__ void split_bf16_kernel(const float* __restrict__ in,
                                  __nv_bfloat16* __restrict__ hi,
                                  __nv_bfloat16* __restrict__ lo, int n4)
{
    int i = blockIdx.x * blockDim.x + threadIdx.x;
    if (i >= n4) return;
    float4 v = ((const float4*)in)[i];
    uint32_t h01, l01, h23, l23;
    split_pack2(v.x, v.y, h01, l01);
    split_pack2(v.z, v.w, h23, l23);
    uint32_t* hp = (uint32_t*)(hi + (size_t)i * 4);
    uint32_t* lp = (uint32_t*)(lo + (size_t)i * 4);
    hp[0] = h01; hp[1] = h23;
    lp[0] = l01; lp[1] = l23;
}

// ---------------------------------------------------------------------------
// mma.sync GEMM: C[M,N] = A[M,K] @ W[N,K]^T  (bf16x3 split, fp32 accum)
// CTA 128x128, BK=32, 256 threads, warp tile 64x32.
// SPLIT_OUT: write hi/lo bf16 planes instead of fp32.
// ---------------------------------------------------------------------------
#define BM 128
#define BN 128
#define BK 32
#define TILEB  (BM * BK * 2)
#define STAGEB (4 * TILEB)
#define GEMM_SMEM (2 * STAGEB)   // 64 KB

template<bool SPLIT_OUT>
__global__ __launch_bounds__(256, 1)
void gemm_mma(const __nv_bfloat16* __restrict__ Ahi, const __nv_bfloat16* __restrict__ Alo,
              const __nv_bfloat16* __restrict__ Whi, const __nv_bfloat16* __restrict__ Wlo,
              float* __restrict__ C,
              __nv_bfloat16* __restrict__ Chi, __nv_bfloat16* __restrict__ Clo,
              int N, int K)
{
    extern __shared__ char smem[];
    const uint32_t sbase = smem_u32(smem);
    const int tid  = threadIdx.x;
    const int wid  = tid >> 5;
    const int lane = tid & 31;
    const int wm   = wid & 1;
    const int wn   = wid >> 1;
    const int m0   = blockIdx.y * BM;
    const int n0   = blockIdx.x * BN;

    const int lrow = tid >> 1;
    const int lc0  = (tid & 1) * 2;
    const int lswz = (lrow >> 1) & 3;

    const __nv_bfloat16* srcs[4];
    srcs[0] = Ahi + (size_t)(m0 + lrow) * K;
    srcs[1] = Alo + (size_t)(m0 + lrow) * K;
    srcs[2] = Whi + (size_t)(n0 + lrow) * K;
    srcs[3] = Wlo + (size_t)(n0 + lrow) * K;

    auto LOAD = [&](int s, int c) {
#pragma unroll
        for (int a = 0; a < 4; a++) {
#pragma unroll
            for (int j = 0; j < 2; j++) {
                const int cl = lc0 + j;
                const uint32_t dst = sbase + s * STAGEB + a * TILEB
                                   + lrow * 64 + ((cl ^ lswz) << 4);
                CP_ASYNC16(dst, srcs[a] + (size_t)c * BK + cl * 8);
            }
        }
    };

    float acc[4][4][4];
#pragma unroll
    for (int i = 0; i < 4; i++)
#pragma unroll
        for (int j = 0; j < 4; j++)
#pragma unroll
            for (int k = 0; k < 4; k++) acc[i][j][k] = 0.f;

    const int NC = K / BK;
    LOAD(0, 0);
    CP_COMMIT();

    const int mi     = lane >> 3;
    const int row_in = lane & 7;
    const int a_rowadd = (mi & 1) * 8;
    const int a_cadd   = mi >> 1;
    const int b_rowadd = (mi >> 1) * 8;
    const int b_cadd   = mi & 1;

    for (int c = 0; c < NC; c++) {
        const int s = c & 1;
        if (c + 1 < NC) {
            LOAD(s ^ 1, c + 1);
            CP_COMMIT();
            asm volatile("cp.async.wait_group 1;" ::: "memory");
        } else {
            asm volatile("cp.async.wait_group 0;" ::: "memory");
        }
        __syncthreads();

        const uint32_t st = sbase + s * STAGEB;
#pragma unroll
        for (int ks = 0; ks < 2; ks++) {
            uint32_t ah[4][4], al[4][4], bh[8], bl[8];
#pragma unroll
            for (int mt = 0; mt < 4; mt++) {
                const int r  = wm * 64 + mt * 16 + a_rowadd + row_in;
                const int cl = ks * 2 + a_cadd;
                const uint32_t off = r * 64 + ((cl ^ ((r >> 1) & 3)) << 4);
                ldsm_x4(ah[mt], st + 0 * TILEB + off);
                ldsm_x4(al[mt], st + 1 * TILEB + off);
            }
#pragma unroll
            for (int p = 0; p < 2; p++) {
                const int r  = wn * 32 + p * 16 + b_rowadd + row_in;
                const int cl = ks * 2 + b_cadd;
                const uint32_t off = r * 64 + ((cl ^ ((r >> 1) & 3)) << 4);
                ldsm_x4(&bh[p * 4], st + 2 * TILEB + off);
                ldsm_x4(&bl[p * 4], st + 3 * TILEB + off);
            }
#pragma unroll
            for (int mt = 0; mt < 4; mt++)
#pragma unroll
                for (int nt = 0; nt < 4; nt++) {
                    mma16816(acc[mt][nt], ah[mt], &bh[nt * 2]);
                    mma16816(acc[mt][nt], ah[mt], &bl[nt * 2]);
                    mma16816(acc[mt][nt], al[mt], &bh[nt * 2]);
                }
        }
        __syncthreads();
    }

#pragma unroll
    for (int mt = 0; mt < 4; mt++) {
#pragma unroll
        for (int nt = 0; nt < 4; nt++) {
            const int row = m0 + wm * 64 + mt * 16 + (lane >> 2);
            const int col = n0 + wn * 32 + nt * 8 + (lane & 3) * 2;
            if (SPLIT_OUT) {
                uint32_t h, l;
                split_pack2(acc[mt][nt][0], acc[mt][nt][1], h, l);
                *(uint32_t*)(Chi + (size_t)row * N + col) = h;
                *(uint32_t*)(Clo + (size_t)row * N + col) = l;
                split_pack2(acc[mt][nt][2], acc[mt][nt][3], h, l);
                *(uint32_t*)(Chi + (size_t)(row + 8) * N + col) = h;
                *(uint32_t*)(Clo + (size_t)(row + 8) * N + col) = l;
            } else {
                *(float2*)(C + (size_t)row * N + col) =
                    make_float2(acc[mt][nt][0], acc[mt][nt][1]);
                *(float2*)(C + (size_t)(row + 8) * N + col) =
                    make_float2(acc[mt][nt][2], acc[mt][nt][3]);
            }
        }
    }
}

// ---------------------------------------------------------------------------
// Tensor-core flash attention (causal). 64q x 64k tiles, Dh=64.
// 128 threads = 4 warps; warp wq owns q rows [wq*16, wq*16+16).
// S = QhiKhi + QhiKlo + QloKhi ; O = PhiVhi + PhiVlo + PloVhi.
// Smem: Q planes + double-buffered K/V planes, 128B rows, XOR-8 swizzle.
// ---------------------------------------------------------------------------
#define AQ_HI   0
#define AQ_LO   8192
#define AKV(s)  (16384 + (s) * 32768)   // KHI, then +8192 KLO, +16384 VHI, +24576 VLO
#define ATTN_SMEM 81920

__global__ __launch_bounds__(128)
void attn_mma_kernel(const __nv_bfloat16* __restrict__ qkv_hi,
                     const __nv_bfloat16* __restrict__ qkv_lo,
                     __nv_bfloat16* __restrict__ y_hi,
                     __nv_bfloat16* __restrict__ y_lo)
{
    extern __shared__ char smem[];
    const uint32_t sb = smem_u32(smem);
    const int tid  = threadIdx.x;
    const int wq   = tid >> 5;
    const int lane = tid & 31;
    const int qt   = gridDim.x - 1 - blockIdx.x;
    const int h    = blockIdx.y;
    const int b    = blockIdx.z;
    const int q0   = qt * 64;

    const int lrow = tid >> 1;            // 0..63
    const int lcb  = (tid & 1) * 4;       // chunk base 0 or 4
    const size_t qrow_g = (size_t)(b * SEQ + q0 + lrow) * QKV_F + h * HDIM;

    // ---- load Q tile (hi/lo) ----
#pragma unroll
    for (int c = 0; c < 4; c++) {
        const int cl = lcb + c;
        const uint32_t so = lrow * 128 + ((cl ^ (lrow & 7)) << 4);
        CP_ASYNC16(sb + AQ_HI + so, qkv_hi + qrow_g + cl * 8);
        CP_ASYNC16(sb + AQ_LO + so, qkv_lo + qrow_g + cl * 8);
    }
    // ---- K/V tile loader ----
    auto LOAD_KV = [&](int kt, int s) {
        const size_t krow_g = (size_t)(b * SEQ + kt * 64 + lrow) * QKV_F + D_MODEL + h * HDIM;
        const size_t vrow_g = krow_g + D_MODEL;
        const uint32_t base = sb + AKV(s);
#pragma unroll
        for (int c = 0; c < 4; c++) {
            const int cl = lcb + c;
            const uint32_t so = lrow * 128 + ((cl ^ (lrow & 7)) << 4);
            CP_ASYNC16(base +     0 + so, qkv_hi + krow_g + cl * 8);
            CP_ASYNC16(base +  8192 + so, qkv_lo + krow_g + cl * 8);
            CP_ASYNC16(base + 16384 + so, qkv_hi + vrow_g + cl * 8);
            CP_ASYNC16(base + 24576 + so, qkv_lo + vrow_g + cl * 8);
        }
    };

    LOAD_KV(0, 0);
    CP_COMMIT();

    const int mi     = lane >> 3;
    const int row_in = lane & 7;
    const int r0     = lane >> 2;         // acc row within 16
    const int c0     = (lane & 3) * 2;    // acc col within 8

    uint32_t qh[4][4], ql[4][4];          // Q fragments, hoisted
    float oacc[8][4];
    float m0 = -1e30f, m1 = -1e30f, l0 = 0.f, l1 = 0.f;
#pragma unroll
    for (int i = 0; i < 8; i++)
#pragma unroll
        for (int j = 0; j < 4; j++) oacc[i][j] = 0.f;

    const float LSCALE = 0.18033688f;     // 0.125 * log2(e)

    for (int kt = 0; kt <= qt; kt++) {
        const int s = kt & 1;
        if (kt < qt) {
            LOAD_KV(kt + 1, s ^ 1);
            CP_COMMIT();
            asm volatile("cp.async.wait_group 1;" ::: "memory");
        } else {
            asm volatile("cp.async.wait_group 0;" ::: "memory");
        }
        __syncthreads();

        if (kt == 0) {
            // Q fragments: A layout m16k16
#pragma unroll
            for (int ks = 0; ks < 4; ks++) {
                const int r  = wq * 16 + (mi & 1) * 8 + row_in;
                const int cl = ks * 2 + (mi >> 1);
                const uint32_t off = r * 128 + ((cl ^ (r & 7)) << 4);
                ldsm_x4(qh[ks], sb + AQ_HI + off);
                ldsm_x4(ql[ks], sb + AQ_LO + off);
            }
        }

        // ---- S = Q K^T ----
        float sacc[8][4];
#pragma unroll
        for (int i = 0; i < 8; i++)
#pragma unroll
            for (int j = 0; j < 4; j++) sacc[i][j] = 0.f;

        const uint32_t kbase = sb + AKV(s);
#pragma unroll
        for (int ks = 0; ks < 4; ks++) {
#pragma unroll
            for (int ntp = 0; ntp < 4; ntp++) {
                uint32_t kh[4], kl[4];
                const int r  = ntp * 16 + (mi >> 1) * 8 + row_in;
                const int cl = ks * 2 + (mi & 1);
                const uint32_t off = r * 128 + ((cl ^ (r & 7)) << 4);
                ldsm_x4(kh, kbase + off);
                ldsm_x4(kl, kbase + 8192 + off);
                mma16816(sacc[ntp * 2],     qh[ks], &kh[0]);
                mma16816(sacc[ntp * 2],     qh[ks], &kl[0]);
                mma16816(sacc[ntp * 2],     ql[ks], &kh[0]);
                mma16816(sacc[ntp * 2 + 1], qh[ks], &kh[2]);
                mma16816(sacc[ntp * 2 + 1], qh[ks], &kl[2]);
                mma16816(sacc[ntp * 2 + 1], ql[ks], &kh[2]);
            }
        }

        // ---- causal mask (diag tile only) ----
        if (kt == qt) {
            const int row_a = q0 + wq * 16 + r0;
            const int row_b = row_a + 8;
#pragma unroll
            for (int nt = 0; nt < 8; nt++) {
                const int col = q0 + nt * 8 + c0;
                if (col     > row_a) sacc[nt][0] = -1e30f;
                if (col + 1 > row_a) sacc[nt][1] = -1e30f;
                if (col     > row_b) sacc[nt][2] = -1e30f;
                if (col + 1 > row_b) sacc[nt][3] = -1e30f;
            }
        }

        // ---- online softmax ----
        float mx0 = -1e30f, mx1 = -1e30f;
#pragma unroll
        for (int nt = 0; nt < 8; nt++) {
            mx0 = fmaxf(mx0, fmaxf(sacc[nt][0], sacc[nt][1]));
            mx1 = fmaxf(mx1, fmaxf(sacc[nt][2], sacc[nt][3]));
        }
        mx0 = fmaxf(mx0, __shfl_xor_sync(0xffffffffu, mx0, 1));
        mx0 = fmaxf(mx0, __shfl_xor_sync(0xffffffffu, mx0, 2));
        mx1 = fmaxf(mx1, __shfl_xor_sync(0xffffffffu, mx1, 1));
        mx1 = fmaxf(mx1, __shfl_xor_sync(0xffffffffu, mx1, 2));
        const float mn0 = fmaxf(m0, mx0), mn1 = fmaxf(m1, mx1);
        const float al0 = ex2((m0 - mn0) * LSCALE);
        const float al1 = ex2((m1 - mn1) * LSCALE);
        m0 = mn0; m1 = mn1;

        float rs0 = 0.f, rs1 = 0.f;
#pragma unroll
        for (int nt = 0; nt < 8; nt++) {
            sacc[nt][0] = ex2((sacc[nt][0] - mn0) * LSCALE);
            sacc[nt][1] = ex2((sacc[nt][1] - mn0) * LSCALE);
            sacc[nt][2] = ex2((sacc[nt][2] - mn1) * LSCALE);
            sacc[nt][3] = ex2((sacc[nt][3] - mn1) * LSCALE);
            rs0 += sacc[nt][0] + sacc[nt][1];
            rs1 += sacc[nt][2] + sacc[nt][3];
        }
        rs0 += __shfl_xor_sync(0xffffffffu, rs0, 1);
        rs0 += __shfl_xor_sync(0xffffffffu, rs0, 2);
        rs1 += __shfl_xor_sync(0xffffffffu, rs1, 1);
        rs1 += __shfl_xor_sync(0xffffffffu, rs1, 2);
        l0 = l0 * al0 + rs0;
        l1 = l1 * al1 + rs1;
#pragma unroll
        for (int nt = 0; nt < 8; nt++) {
            oacc[nt][0] *= al0; oacc[nt][1] *= al0;
            oacc[nt][2] *= al1; oacc[nt][3] *= al1;
        }

        // ---- O += P V ----
        const uint32_t vbase = sb + AKV(s) + 16384;
#pragma unroll
        for (int kb = 0; kb < 4; kb++) {
            uint32_t ph[4], pl[4];
            split_pack2(sacc[2 * kb][0],     sacc[2 * kb][1],     ph[0], pl[0]);
            split_pack2(sacc[2 * kb][2],     sacc[2 * kb][3],     ph[1], pl[1]);
            split_pack2(sacc[2 * kb + 1][0], sacc[2 * kb + 1][1], ph[2], pl[2]);
            split_pack2(sacc[2 * kb + 1][2], sacc[2 * kb + 1][3], ph[3], pl[3]);
#pragma unroll
            for (int dp = 0; dp < 4; dp++) {
                uint32_t vh[4], vl[4];
                const int kr = kb * 16 + (mi & 1) * 8 + row_in;
                const int cl = dp * 2 + (mi >> 1);
                const uint32_t off = kr * 128 + ((cl ^ (kr & 7)) << 4);
                ldsm_x4_t(vh, vbase + off);
                ldsm_x4_t(vl, vbase + 8192 + off);
                mma16816(oacc[dp * 2],     ph, &vh[0]);
                mma16816(oacc[dp * 2],     ph, &vl[0]);
                mma16816(oacc[dp * 2],     pl, &vh[0]);
                mma16816(oacc[dp * 2 + 1], ph, &vh[2]);
                mma16816(oacc[dp * 2 + 1], ph, &vl[2]);
                mma16816(oacc[dp * 2 + 1], pl, &vh[2]);
            }
        }
        __syncthreads();
    }

    // ---- normalize + write y hi/lo ----
    const float inv0 = 1.f / l0, inv1 = 1.f / l1;
    const int row_a = b * SEQ + q0 + wq * 16 + r0;
    const int col_b = h * HDIM + c0;
#pragma unroll
    for (int nt = 0; nt < 8; nt++) {
        uint32_t hA, lA, hB, lB;
        split_pack2(oacc[nt][0] * inv0, oacc[nt][1] * inv0, hA, lA);
        split_pack2(oacc[nt][2] * inv1, oacc[nt][3] * inv1, hB, lB);
        const size_t oA = (size_t)row_a * D_MODEL + col_b + nt * 8;
        const size_t oB = (size_t)(row_a + 8) * D_MODEL + col_b + nt * 8;
        *(uint32_t*)(y_hi + oA) = hA;
        *(uint32_t*)(y_lo + oA) = lA;
        *(uint32_t*)(y_hi + oB) = hB;
        *(uint32_t*)(y_lo + oB) = lB;
    }
}

// ---------------------------------------------------------------------------
extern "C" void kernel_launch(void* const* d_in, const int* in_sizes, int n_in,
                              void* d_out, int out_size)
{
    (void)in_sizes; (void)n_in; (void)out_size;
    const float* x      = (const float*)d_in[0];
    const float* w_qkv  = (const float*)d_in[1];
    const float* w_proj = (const float*)d_in[2];
    float* out = (float*)d_out;

    __nv_bfloat16 *qkvh, *qkvl, *xhi, *xlo, *yhi, *ylo, *wqh, *wql, *wph, *wpl;
    cudaGetSymbolAddress((void**)&qkvh, g_qkv_hi);
    cudaGetSymbolAddress((void**)&qkvl, g_qkv_lo);
    cudaGetSymbolAddress((void**)&xhi, g_x_hi);
    cudaGetSymbolAddress((void**)&xlo, g_x_lo);
    cudaGetSymbolAddress((void**)&yhi, g_y_hi);
    cudaGetSymbolAddress((void**)&ylo, g_y_lo);
    cudaGetSymbolAddress((void**)&wqh, g_wqkv_hi);
    cudaGetSymbolAddress((void**)&wql, g_wqkv_lo);
    cudaGetSymbolAddress((void**)&wph, g_wproj_hi);
    cudaGetSymbolAddress((void**)&wpl, g_wproj_lo);

    cudaFuncSetAttribute(gemm_mma<true>,  cudaFuncAttributeMaxDynamicSharedMemorySize, GEMM_SMEM);
    cudaFuncSetAttribute(gemm_mma<false>, cudaFuncAttributeMaxDynamicSharedMemorySize, GEMM_SMEM);
    cudaFuncSetAttribute(attn_mma_kernel, cudaFuncAttributeMaxDynamicSharedMemorySize, ATTN_SMEM);

    const int nX  = MROWS * D_MODEL / 4;
    const int nWq = QKV_F * D_MODEL / 4;
    const int nWp = D_MODEL * D_MODEL / 4;

    split_bf16_kernel<<<(nX + 255) / 256, 256>>>(x, xhi, xlo, nX);
    split_bf16_kernel<<<(nWq + 255) / 256, 256>>>(w_qkv, wqh, wql, nWq);
    split_bf16_kernel<<<(nWp + 255) / 256, 256>>>(w_proj, wph, wpl, nWp);

    // qkv (hi/lo bf16) = x @ w_qkv^T
    gemm_mma<true><<<dim3(QKV_F / BN, MROWS / BM), 256, GEMM_SMEM>>>(
        xhi, xlo, wqh, wql, nullptr, qkvh, qkvl, QKV_F, D_MODEL);

    // attention -> y (hi/lo bf16)
    attn_mma_kernel<<<dim3(SEQ / 64, NHEADS, BATCH), 128, ATTN_SMEM>>>(qkvh, qkvl, yhi, ylo);

    // out = y @ w_proj^T  (fp32)
    gemm_mma<false><<<dim3(D_MODEL / BN, MROWS / BM), 256, GEMM_SMEM>>>(
        yhi, ylo, wph, wpl, out, nullptr, nullptr, D_MODEL, D_MODEL);
}

// round 5
// speedup vs baseline: 2.8546x; 1.7017x over previous
#include <cuda_runtime.h>
#include <cuda_bf16.h>
#include <cstdint>
#include <math.h>

#define D_MODEL 1024
#define QKV_F   3072
#define NHEADS  16
#define HDIM    64
#define BATCH   4
#define SEQ     2048
#define MROWS   (BATCH * SEQ)   // 8192

// ---------------------------------------------------------------------------
// Scratch (__device__ globals; allocation-free rule)
// ---------------------------------------------------------------------------
__device__ __nv_bfloat16 g_qkv_hi[(size_t)MROWS * QKV_F];
__device__ __nv_bfloat16 g_qkv_lo[(size_t)MROWS * QKV_F];
__device__ __nv_bfloat16 g_x_hi[(size_t)MROWS * D_MODEL];
__device__ __nv_bfloat16 g_x_lo[(size_t)MROWS * D_MODEL];
__device__ __nv_bfloat16 g_y_hi[(size_t)MROWS * D_MODEL];
__device__ __nv_bfloat16 g_y_lo[(size_t)MROWS * D_MODEL];
__device__ __nv_bfloat16 g_wqkv_hi[(size_t)QKV_F * D_MODEL];
__device__ __nv_bfloat16 g_wqkv_lo[(size_t)QKV_F * D_MODEL];
__device__ __nv_bfloat16 g_wproj_hi[(size_t)D_MODEL * D_MODEL];
__device__ __nv_bfloat16 g_wproj_lo[(size_t)D_MODEL * D_MODEL];

// ---------------------------------------------------------------------------
// Helpers (base sm_103 ISA: mma.sync / ldmatrix / cp.async)
// ---------------------------------------------------------------------------
__device__ __forceinline__ uint32_t smem_u32(const void* p) {
    uint32_t a;
    asm("{ .reg .u64 t; cvta.to.shared.u64 t, %1; cvt.u32.u64 %0, t; }" : "=r"(a) : "l"(p));
    return a;
}
__device__ __forceinline__ void ldsm_x4(uint32_t* r, uint32_t addr) {
    asm volatile("ldmatrix.sync.aligned.m8n8.x4.shared.b16 {%0,%1,%2,%3}, [%4];"
        : "=r"(r[0]), "=r"(r[1]), "=r"(r[2]), "=r"(r[3]) : "r"(addr));
}
__device__ __forceinline__ void ldsm_x4_t(uint32_t* r, uint32_t addr) {
    asm volatile("ldmatrix.sync.aligned.m8n8.x4.trans.shared.b16 {%0,%1,%2,%3}, [%4];"
        : "=r"(r[0]), "=r"(r[1]), "=r"(r[2]), "=r"(r[3]) : "r"(addr));
}
__device__ __forceinline__ void mma16816(float* d, const uint32_t* a, const uint32_t* b) {
    asm volatile("mma.sync.aligned.m16n8k16.row.col.f32.bf16.bf16.f32 "
        "{%0,%1,%2,%3}, {%4,%5,%6,%7}, {%8,%9}, {%0,%1,%2,%3};"
        : "+f"(d[0]), "+f"(d[1]), "+f"(d[2]), "+f"(d[3])
        : "r"(a[0]), "r"(a[1]), "r"(a[2]), "r"(a[3]), "r"(b[0]), "r"(b[1]));
}
#define CP_ASYNC16(dst, src) \
    asm volatile("cp.async.cg.shared.global [%0], [%1], 16;" :: "r"(dst), "l"(src) : "memory")
#define CP_COMMIT() asm volatile("cp.async.commit_group;" ::: "memory")

__device__ __forceinline__ float ex2(float x) {
    float y; asm("ex2.approx.f32 %0, %1;" : "=f"(y) : "f"(x)); return y;
}
// split x0,x1 into packed bf16x2 hi & lo planes (x0 in low half)
__device__ __forceinline__ void split_pack2(float x0, float x1, uint32_t& hi, uint32_t& lo) {
    __nv_bfloat16 h0 = __float2bfloat16(x0), h1 = __float2bfloat16(x1);
    __nv_bfloat16 l0 = __float2bfloat16(x0 - __bfloat162float(h0));
    __nv_bfloat16 l1 = __float2bfloat16(x1 - __bfloat162float(h1));
    __nv_bfloat162 H(h0, h1), L(l0, l1);
    hi = *reinterpret_cast<uint32_t*>(&H);
    lo = *reinterpret_cast<uint32_t*>(&L);
}

// ---------------------------------------------------------------------------
// fp32 -> (bf16 hi, bf16 lo) elementwise split
// ---------------------------------------------------------------------------
__global__ void split_bf16_kernel(const float* __restrict__ in,
                                  __nv_bfloat16* __restrict__ hi,
                                  __nv_bfloat16* __restrict__ lo, int n4)
{
    int i = blockIdx.x * blockDim.x + threadIdx.x;
    if (i >= n4) return;
    float4 v = ((const float4*)in)[i];
    uint32_t h01, l01, h23, l23;
    split_pack2(v.x, v.y, h01, l01);
    split_pack2(v.z, v.w, h23, l23);
    uint32_t* hp = (uint32_t*)(hi + (size_t)i * 4);
    uint32_t* lp = (uint32_t*)(lo + (size_t)i * 4);
    hp[0] = h01; hp[1] = h23;
    lp[0] = l01; lp[1] = l23;
}

// ---------------------------------------------------------------------------
// mma.sync GEMM: C[M,N] = A[M,K] @ W[N,K]^T  (bf16x3 split, fp32 accum)
// CTA 128x128, BK=32, 256 threads, warp tile 64x32.
// __launch_bounds__(256, 2): cap regs at 128 so 2 CTAs co-reside per SM.
// ---------------------------------------------------------------------------
#define BM 128
#define BN 128
#define BK 32
#define TILEB  (BM * BK * 2)
#define STAGEB (4 * TILEB)
#define GEMM_SMEM (2 * STAGEB)   // 64 KB

template<bool SPLIT_OUT>
__global__ __launch_bounds__(256, 2)
void gemm_mma(const __nv_bfloat16* __restrict__ Ahi, const __nv_bfloat16* __restrict__ Alo,
              const __nv_bfloat16* __restrict__ Whi, const __nv_bfloat16* __restrict__ Wlo,
              float* __restrict__ C,
              __nv_bfloat16* __restrict__ Chi, __nv_bfloat16* __restrict__ Clo,
              int N, int K)
{
    extern __shared__ char smem[];
    const uint32_t sbase = smem_u32(smem);
    const int tid  = threadIdx.x;
    const int wid  = tid >> 5;
    const int lane = tid & 31;
    const int wm   = wid & 1;
    const int wn   = wid >> 1;
    const int m0   = blockIdx.y * BM;
    const int n0   = blockIdx.x * BN;

    const int lrow = tid >> 1;
    const int lc0  = (tid & 1) * 2;
    const int lswz = (lrow >> 1) & 3;

    const __nv_bfloat16* srcs[4];
    srcs[0] = Ahi + (size_t)(m0 + lrow) * K;
    srcs[1] = Alo + (size_t)(m0 + lrow) * K;
    srcs[2] = Whi + (size_t)(n0 + lrow) * K;
    srcs[3] = Wlo + (size_t)(n0 + lrow) * K;

    auto LOAD = [&](int s, int c) {
#pragma unroll
        for (int a = 0; a < 4; a++) {
#pragma unroll
            for (int j = 0; j < 2; j++) {
                const int cl = lc0 + j;
                const uint32_t dst = sbase + s * STAGEB + a * TILEB
                                   + lrow * 64 + ((cl ^ lswz) << 4);
                CP_ASYNC16(dst, srcs[a] + (size_t)c * BK + cl * 8);
            }
        }
    };

    float acc[4][4][4];
#pragma unroll
    for (int i = 0; i < 4; i++)
#pragma unroll
        for (int j = 0; j < 4; j++)
#pragma unroll
            for (int k = 0; k < 4; k++) acc[i][j][k] = 0.f;

    const int NC = K / BK;
    LOAD(0, 0);
    CP_COMMIT();

    const int mi     = lane >> 3;
    const int row_in = lane & 7;
    const int a_rowadd = (mi & 1) * 8;
    const int a_cadd   = mi >> 1;
    const int b_rowadd = (mi >> 1) * 8;
    const int b_cadd   = mi & 1;

    for (int c = 0; c < NC; c++) {
        const int s = c & 1;
        if (c + 1 < NC) {
            LOAD(s ^ 1, c + 1);
            CP_COMMIT();
            asm volatile("cp.async.wait_group 1;" ::: "memory");
        } else {
            asm volatile("cp.async.wait_group 0;" ::: "memory");
        }
        __syncthreads();

        const uint32_t st = sbase + s * STAGEB;
#pragma unroll
        for (int ks = 0; ks < 2; ks++) {
            uint32_t ah[4][4], al[4][4], bh[8], bl[8];
#pragma unroll
            for (int mt = 0; mt < 4; mt++) {
                const int r  = wm * 64 + mt * 16 + a_rowadd + row_in;
                const int cl = ks * 2 + a_cadd;
                const uint32_t off = r * 64 + ((cl ^ ((r >> 1) & 3)) << 4);
                ldsm_x4(ah[mt], st + 0 * TILEB + off);
                ldsm_x4(al[mt], st + 1 * TILEB + off);
            }
#pragma unroll
            for (int p = 0; p < 2; p++) {
                const int r  = wn * 32 + p * 16 + b_rowadd + row_in;
                const int cl = ks * 2 + b_cadd;
                const uint32_t off = r * 64 + ((cl ^ ((r >> 1) & 3)) << 4);
                ldsm_x4(&bh[p * 4], st + 2 * TILEB + off);
                ldsm_x4(&bl[p * 4], st + 3 * TILEB + off);
            }
#pragma unroll
            for (int mt = 0; mt < 4; mt++)
#pragma unroll
                for (int nt = 0; nt < 4; nt++) {
                    mma16816(acc[mt][nt], ah[mt], &bh[nt * 2]);
                    mma16816(acc[mt][nt], ah[mt], &bl[nt * 2]);
                    mma16816(acc[mt][nt], al[mt], &bh[nt * 2]);
                }
        }
        __syncthreads();
    }

#pragma unroll
    for (int mt = 0; mt < 4; mt++) {
#pragma unroll
        for (int nt = 0; nt < 4; nt++) {
            const int row = m0 + wm * 64 + mt * 16 + (lane >> 2);
            const int col = n0 + wn * 32 + nt * 8 + (lane & 3) * 2;
            if (SPLIT_OUT) {
                uint32_t h, l;
                split_pack2(acc[mt][nt][0], acc[mt][nt][1], h, l);
                *(uint32_t*)(Chi + (size_t)row * N + col) = h;
                *(uint32_t*)(Clo + (size_t)row * N + col) = l;
                split_pack2(acc[mt][nt][2], acc[mt][nt][3], h, l);
                *(uint32_t*)(Chi + (size_t)(row + 8) * N + col) = h;
                *(uint32_t*)(Clo + (size_t)(row + 8) * N + col) = l;
            } else {
                *(float2*)(C + (size_t)row * N + col) =
                    make_float2(acc[mt][nt][0], acc[mt][nt][1]);
                *(float2*)(C + (size_t)(row + 8) * N + col) =
                    make_float2(acc[mt][nt][2], acc[mt][nt][3]);
            }
        }
    }
}

// ---------------------------------------------------------------------------
// Tensor-core flash attention (causal). 64q x 64k tiles, Dh=64.
// 128 threads = 4 warps; warp wq owns q rows [wq*16, wq*16+16).
// S = QhiKhi + QhiKlo + QloKhi ; O = PhiVhi + PhiVlo + PloVhi.
// ---------------------------------------------------------------------------
#define AQ_HI   0
#define AQ_LO   8192
#define AKV(s)  (16384 + (s) * 32768)   // KHI, +8192 KLO, +16384 VHI, +24576 VLO
#define ATTN_SMEM 81920

__global__ __launch_bounds__(128)
void attn_mma_kernel(const __nv_bfloat16* __restrict__ qkv_hi,
                     const __nv_bfloat16* __restrict__ qkv_lo,
                     __nv_bfloat16* __restrict__ y_hi,
                     __nv_bfloat16* __restrict__ y_lo)
{
    extern __shared__ char smem[];
    const uint32_t sb = smem_u32(smem);
    const int tid  = threadIdx.x;
    const int wq   = tid >> 5;
    const int lane = tid & 31;
    const int qt   = gridDim.x - 1 - blockIdx.x;
    const int h    = blockIdx.y;
    const int b    = blockIdx.z;
    const int q0   = qt * 64;

    const int lrow = tid >> 1;
    const int lcb  = (tid & 1) * 4;
    const size_t qrow_g = (size_t)(b * SEQ + q0 + lrow) * QKV_F + h * HDIM;

#pragma unroll
    for (int c = 0; c < 4; c++) {
        const int cl = lcb + c;
        const uint32_t so = lrow * 128 + ((cl ^ (lrow & 7)) << 4);
        CP_ASYNC16(sb + AQ_HI + so, qkv_hi + qrow_g + cl * 8);
        CP_ASYNC16(sb + AQ_LO + so, qkv_lo + qrow_g + cl * 8);
    }
    auto LOAD_KV = [&](int kt, int s) {
        const size_t krow_g = (size_t)(b * SEQ + kt * 64 + lrow) * QKV_F + D_MODEL + h * HDIM;
        const size_t vrow_g = krow_g + D_MODEL;
        const uint32_t base = sb + AKV(s);
#pragma unroll
        for (int c = 0; c < 4; c++) {
            const int cl = lcb + c;
            const uint32_t so = lrow * 128 + ((cl ^ (lrow & 7)) << 4);
            CP_ASYNC16(base +     0 + so, qkv_hi + krow_g + cl * 8);
            CP_ASYNC16(base +  8192 + so, qkv_lo + krow_g + cl * 8);
            CP_ASYNC16(base + 16384 + so, qkv_hi + vrow_g + cl * 8);
            CP_ASYNC16(base + 24576 + so, qkv_lo + vrow_g + cl * 8);
        }
    };

    LOAD_KV(0, 0);
    CP_COMMIT();

    const int mi     = lane >> 3;
    const int row_in = lane & 7;
    const int r0     = lane >> 2;
    const int c0     = (lane & 3) * 2;

    uint32_t qh[4][4], ql[4][4];
    float oacc[8][4];
    float m0 = -1e30f, m1 = -1e30f, l0 = 0.f, l1 = 0.f;
#pragma unroll
    for (int i = 0; i < 8; i++)
#pragma unroll
        for (int j = 0; j < 4; j++) oacc[i][j] = 0.f;

    const float LSCALE = 0.18033688f;     // 0.125 * log2(e)

    for (int kt = 0; kt <= qt; kt++) {
        const int s = kt & 1;
        if (kt < qt) {
            LOAD_KV(kt + 1, s ^ 1);
            CP_COMMIT();
            asm volatile("cp.async.wait_group 1;" ::: "memory");
        } else {
            asm volatile("cp.async.wait_group 0;" ::: "memory");
        }
        __syncthreads();

        if (kt == 0) {
#pragma unroll
            for (int ks = 0; ks < 4; ks++) {
                const int r  = wq * 16 + (mi & 1) * 8 + row_in;
                const int cl = ks * 2 + (mi >> 1);
                const uint32_t off = r * 128 + ((cl ^ (r & 7)) << 4);
                ldsm_x4(qh[ks], sb + AQ_HI + off);
                ldsm_x4(ql[ks], sb + AQ_LO + off);
            }
        }

        float sacc[8][4];
#pragma unroll
        for (int i = 0; i < 8; i++)
#pragma unroll
            for (int j = 0; j < 4; j++) sacc[i][j] = 0.f;

        const uint32_t kbase = sb + AKV(s);
#pragma unroll
        for (int ks = 0; ks < 4; ks++) {
#pragma unroll
            for (int ntp = 0; ntp < 4; ntp++) {
                uint32_t kh[4], kl[4];
                const int r  = ntp * 16 + (mi >> 1) * 8 + row_in;
                const int cl = ks * 2 + (mi & 1);
                const uint32_t off = r * 128 + ((cl ^ (r & 7)) << 4);
                ldsm_x4(kh, kbase + off);
                ldsm_x4(kl, kbase + 8192 + off);
                mma16816(sacc[ntp * 2],     qh[ks], &kh[0]);
                mma16816(sacc[ntp * 2],     qh[ks], &kl[0]);
                mma16816(sacc[ntp * 2],     ql[ks], &kh[0]);
                mma16816(sacc[ntp * 2 + 1], qh[ks], &kh[2]);
                mma16816(sacc[ntp * 2 + 1], qh[ks], &kl[2]);
                mma16816(sacc[ntp * 2 + 1], ql[ks], &kh[2]);
            }
        }

        if (kt == qt) {
            const int row_a = q0 + wq * 16 + r0;
            const int row_b = row_a + 8;
#pragma unroll
            for (int nt = 0; nt < 8; nt++) {
                const int col = q0 + nt * 8 + c0;
                if (col     > row_a) sacc[nt][0] = -1e30f;
                if (col + 1 > row_a) sacc[nt][1] = -1e30f;
                if (col     > row_b) sacc[nt][2] = -1e30f;
                if (col + 1 > row_b) sacc[nt][3] = -1e30f;
            }
        }

        float mx0 = -1e30f, mx1 = -1e30f;
#pragma unroll
        for (int nt = 0; nt < 8; nt++) {
            mx0 = fmaxf(mx0, fmaxf(sacc[nt][0], sacc[nt][1]));
            mx1 = fmaxf(mx1, fmaxf(sacc[nt][2], sacc[nt][3]));
        }
        mx0 = fmaxf(mx0, __shfl_xor_sync(0xffffffffu, mx0, 1));
        mx0 = fmaxf(mx0, __shfl_xor_sync(0xffffffffu, mx0, 2));
        mx1 = fmaxf(mx1, __shfl_xor_sync(0xffffffffu, mx1, 1));
        mx1 = fmaxf(mx1, __shfl_xor_sync(0xffffffffu, mx1, 2));
        const float mn0 = fmaxf(m0, mx0), mn1 = fmaxf(m1, mx1);
        const float al0 = ex2((m0 - mn0) * LSCALE);
        const float al1 = ex2((m1 - mn1) * LSCALE);
        m0 = mn0; m1 = mn1;

        float rs0 = 0.f, rs1 = 0.f;
#pragma unroll
        for (int nt = 0; nt < 8; nt++) {
            sacc[nt][0] = ex2((sacc[nt][0] - mn0) * LSCALE);
            sacc[nt][1] = ex2((sacc[nt][1] - mn0) * LSCALE);
            sacc[nt][2] = ex2((sacc[nt][2] - mn1) * LSCALE);
            sacc[nt][3] = ex2((sacc[nt][3] - mn1) * LSCALE);
            rs0 += sacc[nt][0] + sacc[nt][1];
            rs1 += sacc[nt][2] + sacc[nt][3];
        }
        rs0 += __shfl_xor_sync(0xffffffffu, rs0, 1);
        rs0 += __shfl_xor_sync(0xffffffffu, rs0, 2);
        rs1 += __shfl_xor_sync(0xffffffffu, rs1, 1);
        rs1 += __shfl_xor_sync(0xffffffffu, rs1, 2);
        l0 = l0 * al0 + rs0;
        l1 = l1 * al1 + rs1;
#pragma unroll
        for (int nt = 0; nt < 8; nt++) {
            oacc[nt][0] *= al0; oacc[nt][1] *= al0;
            oacc[nt][2] *= al1; oacc[nt][3] *= al1;
        }

        const uint32_t vbase = sb + AKV(s) + 16384;
#pragma unroll
        for (int kb = 0; kb < 4; kb++) {
            uint32_t ph[4], pl[4];
            split_pack2(sacc[2 * kb][0],     sacc[2 * kb][1],     ph[0], pl[0]);
            split_pack2(sacc[2 * kb][2],     sacc[2 * kb][3],     ph[1], pl[1]);
            split_pack2(sacc[2 * kb + 1][0], sacc[2 * kb + 1][1], ph[2], pl[2]);
            split_pack2(sacc[2 * kb + 1][2], sacc[2 * kb + 1][3], ph[3], pl[3]);
#pragma unroll
            for (int dp = 0; dp < 4; dp++) {
                uint32_t vh[4], vl[4];
                const int kr = kb * 16 + (mi & 1) * 8 + row_in;
                const int cl = dp * 2 + (mi >> 1);
                const uint32_t off = kr * 128 + ((cl ^ (kr & 7)) << 4);
                ldsm_x4_t(vh, vbase + off);
                ldsm_x4_t(vl, vbase + 8192 + off);
                mma16816(oacc[dp * 2],     ph, &vh[0]);
                mma16816(oacc[dp * 2],     ph, &vl[0]);
                mma16816(oacc[dp * 2],     pl, &vh[0]);
                mma16816(oacc[dp * 2 + 1], ph, &vh[2]);
                mma16816(oacc[dp * 2 + 1], ph, &vl[2]);
                mma16816(oacc[dp * 2 + 1], pl, &vh[2]);
            }
        }
        __syncthreads();
    }

    const float inv0 = 1.f / l0, inv1 = 1.f / l1;
    const int row_a = b * SEQ + q0 + wq * 16 + r0;
    const int col_b = h * HDIM + c0;
#pragma unroll
    for (int nt = 0; nt < 8; nt++) {
        uint32_t hA, lA, hB, lB;
        split_pack2(oacc[nt][0] * inv0, oacc[nt][1] * inv0, hA, lA);
        split_pack2(oacc[nt][2] * inv1, oacc[nt][3] * inv1, hB, lB);
        const size_t oA = (size_t)row_a * D_MODEL + col_b + nt * 8;
        const size_t oB = (size_t)(row_a + 8) * D_MODEL + col_b + nt * 8;
        *(uint32_t*)(y_hi + oA) = hA;
        *(uint32_t*)(y_lo + oA) = lA;
        *(uint32_t*)(y_hi + oB) = hB;
        *(uint32_t*)(y_lo + oB) = lB;
    }
}

// ---------------------------------------------------------------------------
extern "C" void kernel_launch(void* const* d_in, const int* in_sizes, int n_in,
                              void* d_out, int out_size)
{
    (void)in_sizes; (void)n_in; (void)out_size;
    const float* x      = (const float*)d_in[0];
    const float* w_qkv  = (const float*)d_in[1];
    const float* w_proj = (const float*)d_in[2];
    float* out = (float*)d_out;

    __nv_bfloat16 *qkvh, *qkvl, *xhi, *xlo, *yhi, *ylo, *wqh, *wql, *wph, *wpl;
    cudaGetSymbolAddress((void**)&qkvh, g_qkv_hi);
    cudaGetSymbolAddress((void**)&qkvl, g_qkv_lo);
    cudaGetSymbolAddress((void**)&xhi, g_x_hi);
    cudaGetSymbolAddress((void**)&xlo, g_x_lo);
    cudaGetSymbolAddress((void**)&yhi, g_y_hi);
    cudaGetSymbolAddress((void**)&ylo, g_y_lo);
    cudaGetSymbolAddress((void**)&wqh, g_wqkv_hi);
    cudaGetSymbolAddress((void**)&wql, g_wqkv_lo);
    cudaGetSymbolAddress((void**)&wph, g_wproj_hi);
    cudaGetSymbolAddress((void**)&wpl, g_wproj_lo);

    cudaFuncSetAttribute(gemm_mma<true>,  cudaFuncAttributeMaxDynamicSharedMemorySize, GEMM_SMEM);
    cudaFuncSetAttribute(gemm_mma<false>, cudaFuncAttributeMaxDynamicSharedMemorySize, GEMM_SMEM);
    cudaFuncSetAttribute(attn_mma_kernel, cudaFuncAttributeMaxDynamicSharedMemorySize, ATTN_SMEM);

    const int nX  = MROWS * D_MODEL / 4;
    const int nWq = QKV_F * D_MODEL / 4;
    const int nWp = D_MODEL * D_MODEL / 4;

    split_bf16_kernel<<<(nX + 255) / 256, 256>>>(x, xhi, xlo, nX);
    split_bf16_kernel<<<(nWq + 255) / 256, 256>>>(w_qkv, wqh, wql, nWq);
    split_bf16_kernel<<<(nWp + 255) / 256, 256>>>(w_proj, wph, wpl, nWp);

    gemm_mma<true><<<dim3(QKV_F / BN, MROWS / BM), 256, GEMM_SMEM>>>(
        xhi, xlo, wqh, wql, nullptr, qkvh, qkvl, QKV_F, D_MODEL);

    attn_mma_kernel<<<dim3(SEQ / 64, NHEADS, BATCH), 128, ATTN_SMEM>>>(qkvh, qkvl, yhi, ylo);

    gemm_mma<false><<<dim3(D_MODEL / BN, MROWS / BM), 256, GEMM_SMEM>>>(
        yhi, ylo, wph, wpl, out, nullptr, nullptr, D_MODEL, D_MODEL);
}

// round 6
// speedup vs baseline: 2.8849x; 1.0106x over previous
#include <cuda_runtime.h>
#include <cuda_bf16.h>
#include <cstdint>
#include <math.h>

#define D_MODEL 1024
#define QKV_F   3072
#define NHEADS  16
#define HDIM    64
#define BATCH   4
#define SEQ     2048
#define MROWS   (BATCH * SEQ)   // 8192

// ---------------------------------------------------------------------------
// Scratch (__device__ globals; allocation-free rule)
// ---------------------------------------------------------------------------
__device__ __nv_bfloat16 g_qkv_hi[(size_t)MROWS * QKV_F];
__device__ __nv_bfloat16 g_qkv_lo[(size_t)MROWS * QKV_F];
__device__ __nv_bfloat16 g_x_hi[(size_t)MROWS * D_MODEL];
__device__ __nv_bfloat16 g_x_lo[(size_t)MROWS * D_MODEL];
__device__ __nv_bfloat16 g_y_hi[(size_t)MROWS * D_MODEL];
__device__ __nv_bfloat16 g_y_lo[(size_t)MROWS * D_MODEL];
__device__ __nv_bfloat16 g_wqkv_hi[(size_t)QKV_F * D_MODEL];
__device__ __nv_bfloat16 g_wqkv_lo[(size_t)QKV_F * D_MODEL];
__device__ __nv_bfloat16 g_wproj_hi[(size_t)D_MODEL * D_MODEL];
__device__ __nv_bfloat16 g_wproj_lo[(size_t)D_MODEL * D_MODEL];

// ---------------------------------------------------------------------------
// Helpers (base sm_103 ISA: mma.sync / ldmatrix / cp.async)
// ---------------------------------------------------------------------------
__device__ __forceinline__ uint32_t smem_u32(const void* p) {
    uint32_t a;
    asm("{ .reg .u64 t; cvta.to.shared.u64 t, %1; cvt.u32.u64 %0, t; }" : "=r"(a) : "l"(p));
    return a;
}
__device__ __forceinline__ void ldsm_x4(uint32_t* r, uint32_t addr) {
    asm volatile("ldmatrix.sync.aligned.m8n8.x4.shared.b16 {%0,%1,%2,%3}, [%4];"
        : "=r"(r[0]), "=r"(r[1]), "=r"(r[2]), "=r"(r[3]) : "r"(addr));
}
__device__ __forceinline__ void ldsm_x4_t(uint32_t* r, uint32_t addr) {
    asm volatile("ldmatrix.sync.aligned.m8n8.x4.trans.shared.b16 {%0,%1,%2,%3}, [%4];"
        : "=r"(r[0]), "=r"(r[1]), "=r"(r[2]), "=r"(r[3]) : "r"(addr));
}
__device__ __forceinline__ void mma16816(float* d, const uint32_t* a, const uint32_t* b) {
    asm volatile("mma.sync.aligned.m16n8k16.row.col.f32.bf16.bf16.f32 "
        "{%0,%1,%2,%3}, {%4,%5,%6,%7}, {%8,%9}, {%0,%1,%2,%3};"
        : "+f"(d[0]), "+f"(d[1]), "+f"(d[2]), "+f"(d[3])
        : "r"(a[0]), "r"(a[1]), "r"(a[2]), "r"(a[3]), "r"(b[0]), "r"(b[1]));
}
#define CP_ASYNC16(dst, src) \
    asm volatile("cp.async.cg.shared.global [%0], [%1], 16;" :: "r"(dst), "l"(src) : "memory")
#define CP_COMMIT() asm volatile("cp.async.commit_group;" ::: "memory")

__device__ __forceinline__ float ex2(float x) {
    float y; asm("ex2.approx.f32 %0, %1;" : "=f"(y) : "f"(x)); return y;
}
// split x0,x1 into packed bf16x2 hi & lo planes (x0 in low half)
__device__ __forceinline__ void split_pack2(float x0, float x1, uint32_t& hi, uint32_t& lo) {
    __nv_bfloat16 h0 = __float2bfloat16(x0), h1 = __float2bfloat16(x1);
    __nv_bfloat16 l0 = __float2bfloat16(x0 - __bfloat162float(h0));
    __nv_bfloat16 l1 = __float2bfloat16(x1 - __bfloat162float(h1));
    __nv_bfloat162 H(h0, h1), L(l0, l1);
    hi = *reinterpret_cast<uint32_t*>(&H);
    lo = *reinterpret_cast<uint32_t*>(&L);
}

// ---------------------------------------------------------------------------
// fp32 -> (bf16 hi, bf16 lo) elementwise split
// ---------------------------------------------------------------------------
__global__ void split_bf16_kernel(const float* __restrict__ in,
                                  __nv_bfloat16* __restrict__ hi,
                                  __nv_bfloat16* __restrict__ lo, int n4)
{
    int i = blockIdx.x * blockDim.x + threadIdx.x;
    if (i >= n4) return;
    float4 v = ((const float4*)in)[i];
    uint32_t h01, l01, h23, l23;
    split_pack2(v.x, v.y, h01, l01);
    split_pack2(v.z, v.w, h23, l23);
    uint32_t* hp = (uint32_t*)(hi + (size_t)i * 4);
    uint32_t* lp = (uint32_t*)(lo + (size_t)i * 4);
    hp[0] = h01; hp[1] = h23;
    lp[0] = l01; lp[1] = l23;
}

// ---------------------------------------------------------------------------
// mma.sync GEMM: C[M,N] = A[M,K] @ W[N,K]^T  (bf16x3 split, fp32 accum)
// CTA 128x128, BK=32, 256 threads, warp tile 64x32.
// 3-stage cp.async pipeline; __launch_bounds__(256,2) keeps 2 CTAs/SM.
// ---------------------------------------------------------------------------
#define BM 128
#define BN 128
#define BK 32
#define NSTAGE 3
#define TILEB  (BM * BK * 2)
#define STAGEB (4 * TILEB)
#define GEMM_SMEM (NSTAGE * STAGEB)   // 96 KB

template<bool SPLIT_OUT>
__global__ __launch_bounds__(256, 2)
void gemm_mma(const __nv_bfloat16* __restrict__ Ahi, const __nv_bfloat16* __restrict__ Alo,
              const __nv_bfloat16* __restrict__ Whi, const __nv_bfloat16* __restrict__ Wlo,
              float* __restrict__ C,
              __nv_bfloat16* __restrict__ Chi, __nv_bfloat16* __restrict__ Clo,
              int N, int K)
{
    extern __shared__ char smem[];
    const uint32_t sbase = smem_u32(smem);
    const int tid  = threadIdx.x;
    const int wid  = tid >> 5;
    const int lane = tid & 31;
    const int wm   = wid & 1;
    const int wn   = wid >> 1;
    const int m0   = blockIdx.y * BM;
    const int n0   = blockIdx.x * BN;

    const int lrow = tid >> 1;
    const int lc0  = (tid & 1) * 2;
    const int lswz = (lrow >> 1) & 3;

    const __nv_bfloat16* srcs[4];
    srcs[0] = Ahi + (size_t)(m0 + lrow) * K;
    srcs[1] = Alo + (size_t)(m0 + lrow) * K;
    srcs[2] = Whi + (size_t)(n0 + lrow) * K;
    srcs[3] = Wlo + (size_t)(n0 + lrow) * K;

    auto LOAD = [&](int s, int c) {
#pragma unroll
        for (int a = 0; a < 4; a++) {
#pragma unroll
            for (int j = 0; j < 2; j++) {
                const int cl = lc0 + j;
                const uint32_t dst = sbase + s * STAGEB + a * TILEB
                                   + lrow * 64 + ((cl ^ lswz) << 4);
                CP_ASYNC16(dst, srcs[a] + (size_t)c * BK + cl * 8);
            }
        }
    };

    float acc[4][4][4];
#pragma unroll
    for (int i = 0; i < 4; i++)
#pragma unroll
        for (int j = 0; j < 4; j++)
#pragma unroll
            for (int k = 0; k < 4; k++) acc[i][j][k] = 0.f;

    const int NC = K / BK;
    // prologue: stages 0 and 1 in flight
    LOAD(0, 0);
    CP_COMMIT();
    LOAD(1, 1);
    CP_COMMIT();

    const int mi     = lane >> 3;
    const int row_in = lane & 7;
    const int a_rowadd = (mi & 1) * 8;
    const int a_cadd   = mi >> 1;
    const int b_rowadd = (mi >> 1) * 8;
    const int b_cadd   = mi & 1;

    int s = 0;
    for (int c = 0; c < NC; c++) {
        // issue chunk c+2 into stage (s+2)%3 (that buffer was last read for
        // chunk c-1; the trailing __syncthreads of iter c-1 protects it)
        if (c + 2 < NC) {
            LOAD((s + 2 >= NSTAGE) ? s + 2 - NSTAGE : s + 2, c + 2);
            CP_COMMIT();
            asm volatile("cp.async.wait_group 2;" ::: "memory");
        } else if (c + 1 < NC) {
            asm volatile("cp.async.wait_group 1;" ::: "memory");
        } else {
            asm volatile("cp.async.wait_group 0;" ::: "memory");
        }
        __syncthreads();

        const uint32_t st = sbase + s * STAGEB;
#pragma unroll
        for (int ks = 0; ks < 2; ks++) {
            uint32_t ah[4][4], al[4][4], bh[8], bl[8];
#pragma unroll
            for (int mt = 0; mt < 4; mt++) {
                const int r  = wm * 64 + mt * 16 + a_rowadd + row_in;
                const int cl = ks * 2 + a_cadd;
                const uint32_t off = r * 64 + ((cl ^ ((r >> 1) & 3)) << 4);
                ldsm_x4(ah[mt], st + 0 * TILEB + off);
                ldsm_x4(al[mt], st + 1 * TILEB + off);
            }
#pragma unroll
            for (int p = 0; p < 2; p++) {
                const int r  = wn * 32 + p * 16 + b_rowadd + row_in;
                const int cl = ks * 2 + b_cadd;
                const uint32_t off = r * 64 + ((cl ^ ((r >> 1) & 3)) << 4);
                ldsm_x4(&bh[p * 4], st + 2 * TILEB + off);
                ldsm_x4(&bl[p * 4], st + 3 * TILEB + off);
            }
#pragma unroll
            for (int mt = 0; mt < 4; mt++)
#pragma unroll
                for (int nt = 0; nt < 4; nt++) {
                    mma16816(acc[mt][nt], ah[mt], &bh[nt * 2]);
                    mma16816(acc[mt][nt], ah[mt], &bl[nt * 2]);
                    mma16816(acc[mt][nt], al[mt], &bh[nt * 2]);
                }
        }
        __syncthreads();
        s = (s + 1 >= NSTAGE) ? 0 : s + 1;
    }

#pragma unroll
    for (int mt = 0; mt < 4; mt++) {
#pragma unroll
        for (int nt = 0; nt < 4; nt++) {
            const int row = m0 + wm * 64 + mt * 16 + (lane >> 2);
            const int col = n0 + wn * 32 + nt * 8 + (lane & 3) * 2;
            if (SPLIT_OUT) {
                uint32_t h, l;
                split_pack2(acc[mt][nt][0], acc[mt][nt][1], h, l);
                *(uint32_t*)(Chi + (size_t)row * N + col) = h;
                *(uint32_t*)(Clo + (size_t)row * N + col) = l;
                split_pack2(acc[mt][nt][2], acc[mt][nt][3], h, l);
                *(uint32_t*)(Chi + (size_t)(row + 8) * N + col) = h;
                *(uint32_t*)(Clo + (size_t)(row + 8) * N + col) = l;
            } else {
                *(float2*)(C + (size_t)row * N + col) =
                    make_float2(acc[mt][nt][0], acc[mt][nt][1]);
                *(float2*)(C + (size_t)(row + 8) * N + col) =
                    make_float2(acc[mt][nt][2], acc[mt][nt][3]);
            }
        }
    }
}

// ---------------------------------------------------------------------------
// Tensor-core flash attention (causal). 64q x 64k tiles, Dh=64.
// (unchanged from round 5)
// ---------------------------------------------------------------------------
#define AQ_HI   0
#define AQ_LO   8192
#define AKV(s)  (16384 + (s) * 32768)
#define ATTN_SMEM 81920

__global__ __launch_bounds__(128)
void attn_mma_kernel(const __nv_bfloat16* __restrict__ qkv_hi,
                     const __nv_bfloat16* __restrict__ qkv_lo,
                     __nv_bfloat16* __restrict__ y_hi,
                     __nv_bfloat16* __restrict__ y_lo)
{
    extern __shared__ char smem[];
    const uint32_t sb = smem_u32(smem);
    const int tid  = threadIdx.x;
    const int wq   = tid >> 5;
    const int lane = tid & 31;
    const int qt   = gridDim.x - 1 - blockIdx.x;
    const int h    = blockIdx.y;
    const int b    = blockIdx.z;
    const int q0   = qt * 64;

    const int lrow = tid >> 1;
    const int lcb  = (tid & 1) * 4;
    const size_t qrow_g = (size_t)(b * SEQ + q0 + lrow) * QKV_F + h * HDIM;

#pragma unroll
    for (int c = 0; c < 4; c++) {
        const int cl = lcb + c;
        const uint32_t so = lrow * 128 + ((cl ^ (lrow & 7)) << 4);
        CP_ASYNC16(sb + AQ_HI + so, qkv_hi + qrow_g + cl * 8);
        CP_ASYNC16(sb + AQ_LO + so, qkv_lo + qrow_g + cl * 8);
    }
    auto LOAD_KV = [&](int kt, int s) {
        const size_t krow_g = (size_t)(b * SEQ + kt * 64 + lrow) * QKV_F + D_MODEL + h * HDIM;
        const size_t vrow_g = krow_g + D_MODEL;
        const uint32_t base = sb + AKV(s);
#pragma unroll
        for (int c = 0; c < 4; c++) {
            const int cl = lcb + c;
            const uint32_t so = lrow * 128 + ((cl ^ (lrow & 7)) << 4);
            CP_ASYNC16(base +     0 + so, qkv_hi + krow_g + cl * 8);
            CP_ASYNC16(base +  8192 + so, qkv_lo + krow_g + cl * 8);
            CP_ASYNC16(base + 16384 + so, qkv_hi + vrow_g + cl * 8);
            CP_ASYNC16(base + 24576 + so, qkv_lo + vrow_g + cl * 8);
        }
    };

    LOAD_KV(0, 0);
    CP_COMMIT();

    const int mi     = lane >> 3;
    const int row_in = lane & 7;
    const int r0     = lane >> 2;
    const int c0     = (lane & 3) * 2;

    uint32_t qh[4][4], ql[4][4];
    float oacc[8][4];
    float m0 = -1e30f, m1 = -1e30f, l0 = 0.f, l1 = 0.f;
#pragma unroll
    for (int i = 0; i < 8; i++)
#pragma unroll
        for (int j = 0; j < 4; j++) oacc[i][j] = 0.f;

    const float LSCALE = 0.18033688f;     // 0.125 * log2(e)

    for (int kt = 0; kt <= qt; kt++) {
        const int s = kt & 1;
        if (kt < qt) {
            LOAD_KV(kt + 1, s ^ 1);
            CP_COMMIT();
            asm volatile("cp.async.wait_group 1;" ::: "memory");
        } else {
            asm volatile("cp.async.wait_group 0;" ::: "memory");
        }
        __syncthreads();

        if (kt == 0) {
#pragma unroll
            for (int ks = 0; ks < 4; ks++) {
                const int r  = wq * 16 + (mi & 1) * 8 + row_in;
                const int cl = ks * 2 + (mi >> 1);
                const uint32_t off = r * 128 + ((cl ^ (r & 7)) << 4);
                ldsm_x4(qh[ks], sb + AQ_HI + off);
                ldsm_x4(ql[ks], sb + AQ_LO + off);
            }
        }

        float sacc[8][4];
#pragma unroll
        for (int i = 0; i < 8; i++)
#pragma unroll
            for (int j = 0; j < 4; j++) sacc[i][j] = 0.f;

        const uint32_t kbase = sb + AKV(s);
#pragma unroll
        for (int ks = 0; ks < 4; ks++) {
#pragma unroll
            for (int ntp = 0; ntp < 4; ntp++) {
                uint32_t kh[4], kl[4];
                const int r  = ntp * 16 + (mi >> 1) * 8 + row_in;
                const int cl = ks * 2 + (mi & 1);
                const uint32_t off = r * 128 + ((cl ^ (r & 7)) << 4);
                ldsm_x4(kh, kbase + off);
                ldsm_x4(kl, kbase + 8192 + off);
                mma16816(sacc[ntp * 2],     qh[ks], &kh[0]);
                mma16816(sacc[ntp * 2],     qh[ks], &kl[0]);
                mma16816(sacc[ntp * 2],     ql[ks], &kh[0]);
                mma16816(sacc[ntp * 2 + 1], qh[ks], &kh[2]);
                mma16816(sacc[ntp * 2 + 1], qh[ks], &kl[2]);
                mma16816(sacc[ntp * 2 + 1], ql[ks], &kh[2]);
            }
        }

        if (kt == qt) {
            const int row_a = q0 + wq * 16 + r0;
            const int row_b = row_a + 8;
#pragma unroll
            for (int nt = 0; nt < 8; nt++) {
                const int col = q0 + nt * 8 + c0;
                if (col     > row_a) sacc[nt][0] = -1e30f;
                if (col + 1 > row_a) sacc[nt][1] = -1e30f;
                if (col     > row_b) sacc[nt][2] = -1e30f;
                if (col + 1 > row_b) sacc[nt][3] = -1e30f;
            }
        }

        float mx0 = -1e30f, mx1 = -1e30f;
#pragma unroll
        for (int nt = 0; nt < 8; nt++) {
            mx0 = fmaxf(mx0, fmaxf(sacc[nt][0], sacc[nt][1]));
            mx1 = fmaxf(mx1, fmaxf(sacc[nt][2], sacc[nt][3]));
        }
        mx0 = fmaxf(mx0, __shfl_xor_sync(0xffffffffu, mx0, 1));
        mx0 = fmaxf(mx0, __shfl_xor_sync(0xffffffffu, mx0, 2));
        mx1 = fmaxf(mx1, __shfl_xor_sync(0xffffffffu, mx1, 1));
        mx1 = fmaxf(mx1, __shfl_xor_sync(0xffffffffu, mx1, 2));
        const float mn0 = fmaxf(m0, mx0), mn1 = fmaxf(m1, mx1);
        const float al0 = ex2((m0 - mn0) * LSCALE);
        const float al1 = ex2((m1 - mn1) * LSCALE);
        m0 = mn0; m1 = mn1;

        float rs0 = 0.f, rs1 = 0.f;
#pragma unroll
        for (int nt = 0; nt < 8; nt++) {
            sacc[nt][0] = ex2((sacc[nt][0] - mn0) * LSCALE);
            sacc[nt][1] = ex2((sacc[nt][1] - mn0) * LSCALE);
            sacc[nt][2] = ex2((sacc[nt][2] - mn1) * LSCALE);
            sacc[nt][3] = ex2((sacc[nt][3] - mn1) * LSCALE);
            rs0 += sacc[nt][0] + sacc[nt][1];
            rs1 += sacc[nt][2] + sacc[nt][3];
        }
        rs0 += __shfl_xor_sync(0xffffffffu, rs0, 1);
        rs0 += __shfl_xor_sync(0xffffffffu, rs0, 2);
        rs1 += __shfl_xor_sync(0xffffffffu, rs1, 1);
        rs1 += __shfl_xor_sync(0xffffffffu, rs1, 2);
        l0 = l0 * al0 + rs0;
        l1 = l1 * al1 + rs1;
#pragma unroll
        for (int nt = 0; nt < 8; nt++) {
            oacc[nt][0] *= al0; oacc[nt][1] *= al0;
            oacc[nt][2] *= al1; oacc[nt][3] *= al1;
        }

        const uint32_t vbase = sb + AKV(s) + 16384;
#pragma unroll
        for (int kb = 0; kb < 4; kb++) {
            uint32_t ph[4], pl[4];
            split_pack2(sacc[2 * kb][0],     sacc[2 * kb][1],     ph[0], pl[0]);
            split_pack2(sacc[2 * kb][2],     sacc[2 * kb][3],     ph[1], pl[1]);
            split_pack2(sacc[2 * kb + 1][0], sacc[2 * kb + 1][1], ph[2], pl[2]);
            split_pack2(sacc[2 * kb + 1][2], sacc[2 * kb + 1][3], ph[3], pl[3]);
#pragma unroll
            for (int dp = 0; dp < 4; dp++) {
                uint32_t vh[4], vl[4];
                const int kr = kb * 16 + (mi & 1) * 8 + row_in;
                const int cl = dp * 2 + (mi >> 1);
                const uint32_t off = kr * 128 + ((cl ^ (kr & 7)) << 4);
                ldsm_x4_t(vh, vbase + off);
                ldsm_x4_t(vl, vbase + 8192 + off);
                mma16816(oacc[dp * 2],     ph, &vh[0]);
                mma16816(oacc[dp * 2],     ph, &vl[0]);
                mma16816(oacc[dp * 2],     pl, &vh[0]);
                mma16816(oacc[dp * 2 + 1], ph, &vh[2]);
                mma16816(oacc[dp * 2 + 1], ph, &vl[2]);
                mma16816(oacc[dp * 2 + 1], pl, &vh[2]);
            }
        }
        __syncthreads();
    }

    const float inv0 = 1.f / l0, inv1 = 1.f / l1;
    const int row_a = b * SEQ + q0 + wq * 16 + r0;
    const int col_b = h * HDIM + c0;
#pragma unroll
    for (int nt = 0; nt < 8; nt++) {
        uint32_t hA, lA, hB, lB;
        split_pack2(oacc[nt][0] * inv0, oacc[nt][1] * inv0, hA, lA);
        split_pack2(oacc[nt][2] * inv1, oacc[nt][3] * inv1, hB, lB);
        const size_t oA = (size_t)row_a * D_MODEL + col_b + nt * 8;
        const size_t oB = (size_t)(row_a + 8) * D_MODEL + col_b + nt * 8;
        *(uint32_t*)(y_hi + oA) = hA;
        *(uint32_t*)(y_lo + oA) = lA;
        *(uint32_t*)(y_hi + oB) = hB;
        *(uint32_t*)(y_lo + oB) = lB;
    }
}

// ---------------------------------------------------------------------------
extern "C" void kernel_launch(void* const* d_in, const int* in_sizes, int n_in,
                              void* d_out, int out_size)
{
    (void)in_sizes; (void)n_in; (void)out_size;
    const float* x      = (const float*)d_in[0];
    const float* w_qkv  = (const float*)d_in[1];
    const float* w_proj = (const float*)d_in[2];
    float* out = (float*)d_out;

    __nv_bfloat16 *qkvh, *qkvl, *xhi, *xlo, *yhi, *ylo, *wqh, *wql, *wph, *wpl;
    cudaGetSymbolAddress((void**)&qkvh, g_qkv_hi);
    cudaGetSymbolAddress((void**)&qkvl, g_qkv_lo);
    cudaGetSymbolAddress((void**)&xhi, g_x_hi);
    cudaGetSymbolAddress((void**)&xlo, g_x_lo);
    cudaGetSymbolAddress((void**)&yhi, g_y_hi);
    cudaGetSymbolAddress((void**)&ylo, g_y_lo);
    cudaGetSymbolAddress((void**)&wqh, g_wqkv_hi);
    cudaGetSymbolAddress((void**)&wql, g_wqkv_lo);
    cudaGetSymbolAddress((void**)&wph, g_wproj_hi);
    cudaGetSymbolAddress((void**)&wpl, g_wproj_lo);

    cudaFuncSetAttribute(gemm_mma<true>,  cudaFuncAttributeMaxDynamicSharedMemorySize, GEMM_SMEM);
    cudaFuncSetAttribute(gemm_mma<false>, cudaFuncAttributeMaxDynamicSharedMemorySize, GEMM_SMEM);
    cudaFuncSetAttribute(attn_mma_kernel, cudaFuncAttributeMaxDynamicSharedMemorySize, ATTN_SMEM);

    const int nX  = MROWS * D_MODEL / 4;
    const int nWq = QKV_F * D_MODEL / 4;
    const int nWp = D_MODEL * D_MODEL / 4;

    split_bf16_kernel<<<(nX + 255) / 256, 256>>>(x, xhi, xlo, nX);
    split_bf16_kernel<<<(nWq + 255) / 256, 256>>>(w_qkv, wqh, wql, nWq);
    split_bf16_kernel<<<(nWp + 255) / 256, 256>>>(w_proj, wph, wpl, nWp);

    gemm_mma<true><<<dim3(QKV_F / BN, MROWS / BM), 256, GEMM_SMEM>>>(
        xhi, xlo, wqh, wql, nullptr, qkvh, qkvl, QKV_F, D_MODEL);

    attn_mma_kernel<<<dim3(SEQ / 64, NHEADS, BATCH), 128, ATTN_SMEM>>>(qkvh, qkvl, yhi, ylo);

    gemm_mma<false><<<dim3(D_MODEL / BN, MROWS / BM), 256, GEMM_SMEM>>>(
        yhi, ylo, wph, wpl, out, nullptr, nullptr, D_MODEL, D_MODEL);
}

// round 7
// speedup vs baseline: 3.5046x; 1.2148x over previous
#include <cuda_runtime.h>
#include <cuda_fp16.h>
#include <cstdint>
#include <math.h>

#define D_MODEL 1024
#define QKV_F   3072
#define NHEADS  16
#define HDIM    64
#define BATCH   4
#define SEQ     2048
#define MROWS   (BATCH * SEQ)   // 8192

// ---------------------------------------------------------------------------
// Scratch (__device__ globals; allocation-free rule)
// ---------------------------------------------------------------------------
__device__ __half g_qkv_hi[(size_t)MROWS * QKV_F];
__device__ __half g_qkv_lo[(size_t)MROWS * QKV_F];
__device__ __half g_x_hi[(size_t)MROWS * D_MODEL];
__device__ __half g_x_lo[(size_t)MROWS * D_MODEL];
__device__ __half g_y_hi[(size_t)MROWS * D_MODEL];
__device__ __half g_y_lo[(size_t)MROWS * D_MODEL];
__device__ __half g_wqkv_h[(size_t)QKV_F * D_MODEL];
__device__ __half g_wproj_h[(size_t)D_MODEL * D_MODEL];

// ---------------------------------------------------------------------------
// Helpers (base sm_103 ISA: mma.sync / ldmatrix / cp.async)
// ---------------------------------------------------------------------------
__device__ __forceinline__ uint32_t smem_u32(const void* p) {
    uint32_t a;
    asm("{ .reg .u64 t; cvta.to.shared.u64 t, %1; cvt.u32.u64 %0, t; }" : "=r"(a) : "l"(p));
    return a;
}
__device__ __forceinline__ void ldsm_x4(uint32_t* r, uint32_t addr) {
    asm volatile("ldmatrix.sync.aligned.m8n8.x4.shared.b16 {%0,%1,%2,%3}, [%4];"
        : "=r"(r[0]), "=r"(r[1]), "=r"(r[2]), "=r"(r[3]) : "r"(addr));
}
__device__ __forceinline__ void ldsm_x4_t(uint32_t* r, uint32_t addr) {
    asm volatile("ldmatrix.sync.aligned.m8n8.x4.trans.shared.b16 {%0,%1,%2,%3}, [%4];"
        : "=r"(r[0]), "=r"(r[1]), "=r"(r[2]), "=r"(r[3]) : "r"(addr));
}
// fp16 inputs, fp32 accum
__device__ __forceinline__ void mma16816(float* d, const uint32_t* a, const uint32_t* b) {
    asm volatile("mma.sync.aligned.m16n8k16.row.col.f32.f16.f16.f32 "
        "{%0,%1,%2,%3}, {%4,%5,%6,%7}, {%8,%9}, {%0,%1,%2,%3};"
        : "+f"(d[0]), "+f"(d[1]), "+f"(d[2]), "+f"(d[3])
        : "r"(a[0]), "r"(a[1]), "r"(a[2]), "r"(a[3]), "r"(b[0]), "r"(b[1]));
}
#define CP_ASYNC16(dst, src) \
    asm volatile("cp.async.cg.shared.global [%0], [%1], 16;" :: "r"(dst), "l"(src) : "memory")
#define CP_COMMIT() asm volatile("cp.async.commit_group;" ::: "memory")

__device__ __forceinline__ float ex2(float x) {
    float y; asm("ex2.approx.f32 %0, %1;" : "=f"(y) : "f"(x)); return y;
}
// split x0,x1 into packed fp16x2 hi & lo planes (x0 in low half)
__device__ __forceinline__ void split_pack2(float x0, float x1, uint32_t& hi, uint32_t& lo) {
    __half h0 = __float2half_rn(x0), h1 = __float2half_rn(x1);
    __half l0 = __float2half_rn(x0 - __half2float(h0));
    __half l1 = __float2half_rn(x1 - __half2float(h1));
    __half2 H = __halves2half2(h0, h1), L = __halves2half2(l0, l1);
    hi = *reinterpret_cast<uint32_t*>(&H);
    lo = *reinterpret_cast<uint32_t*>(&L);
}

// ---------------------------------------------------------------------------
// fp32 -> (fp16 hi, fp16 lo) elementwise split
// ---------------------------------------------------------------------------
__global__ void split_fp16_kernel(const float* __restrict__ in,
                                  __half* __restrict__ hi,
                                  __half* __restrict__ lo, int n4)
{
    int i = blockIdx.x * blockDim.x + threadIdx.x;
    if (i >= n4) return;
    float4 v = ((const float4*)in)[i];
    uint32_t h01, l01, h23, l23;
    split_pack2(v.x, v.y, h01, l01);
    split_pack2(v.z, v.w, h23, l23);
    uint32_t* hp = (uint32_t*)(hi + (size_t)i * 4);
    uint32_t* lp = (uint32_t*)(lo + (size_t)i * 4);
    hp[0] = h01; hp[1] = h23;
    lp[0] = l01; lp[1] = l23;
}

// fp32 -> fp16 (hi only, for weights)
__global__ void cvt_fp16_kernel(const float* __restrict__ in,
                                __half* __restrict__ hi, int n4)
{
    int i = blockIdx.x * blockDim.x + threadIdx.x;
    if (i >= n4) return;
    float4 v = ((const float4*)in)[i];
    __half2 a = __halves2half2(__float2half_rn(v.x), __float2half_rn(v.y));
    __half2 b = __halves2half2(__float2half_rn(v.z), __float2half_rn(v.w));
    uint32_t* hp = (uint32_t*)(hi + (size_t)i * 4);
    hp[0] = *reinterpret_cast<uint32_t*>(&a);
    hp[1] = *reinterpret_cast<uint32_t*>(&b);
}

// ---------------------------------------------------------------------------
// mma.sync GEMM: C[M,N] = A[M,K] @ W[N,K]^T  (fp16x2: (Ah+Al)*Wh, fp32 accum)
// CTA 128x128, BK=32, 256 threads, warp tile 64x32, 3-stage cp.async.
// Planes per stage: A_hi, A_lo, W_hi  (24 KB). 2 CTAs/SM.
// ---------------------------------------------------------------------------
#define BM 128
#define BN 128
#define BK 32
#define NSTAGE 3
#define TILEB  (BM * BK * 2)
#define STAGEB (3 * TILEB)            // 24 KB
#define GEMM_SMEM (NSTAGE * STAGEB)   // 72 KB

template<bool SPLIT_OUT>
__global__ __launch_bounds__(256, 2)
void gemm_mma(const __half* __restrict__ Ahi, const __half* __restrict__ Alo,
              const __half* __restrict__ Wh,
              float* __restrict__ C,
              __half* __restrict__ Chi, __half* __restrict__ Clo,
              int N, int K)
{
    extern __shared__ char smem[];
    const uint32_t sbase = smem_u32(smem);
    const int tid  = threadIdx.x;
    const int wid  = tid >> 5;
    const int lane = tid & 31;
    const int wm   = wid & 1;
    const int wn   = wid >> 1;
    const int m0   = blockIdx.y * BM;
    const int n0   = blockIdx.x * BN;

    const int lrow = tid >> 1;
    const int lc0  = (tid & 1) * 2;
    const int lswz = (lrow >> 1) & 3;

    const __half* srcs[3];
    srcs[0] = Ahi + (size_t)(m0 + lrow) * K;
    srcs[1] = Alo + (size_t)(m0 + lrow) * K;
    srcs[2] = Wh  + (size_t)(n0 + lrow) * K;

    auto LOAD = [&](int s, int c) {
#pragma unroll
        for (int a = 0; a < 3; a++) {
#pragma unroll
            for (int j = 0; j < 2; j++) {
                const int cl = lc0 + j;
                const uint32_t dst = sbase + s * STAGEB + a * TILEB
                                   + lrow * 64 + ((cl ^ lswz) << 4);
                CP_ASYNC16(dst, srcs[a] + (size_t)c * BK + cl * 8);
            }
        }
    };

    float acc[4][4][4];
#pragma unroll
    for (int i = 0; i < 4; i++)
#pragma unroll
        for (int j = 0; j < 4; j++)
#pragma unroll
            for (int k = 0; k < 4; k++) acc[i][j][k] = 0.f;

    const int NC = K / BK;
    LOAD(0, 0);
    CP_COMMIT();
    LOAD(1, 1);
    CP_COMMIT();

    const int mi     = lane >> 3;
    const int row_in = lane & 7;
    const int a_rowadd = (mi & 1) * 8;
    const int a_cadd   = mi >> 1;
    const int b_rowadd = (mi >> 1) * 8;
    const int b_cadd   = mi & 1;

    int s = 0;
    for (int c = 0; c < NC; c++) {
        if (c + 2 < NC) {
            LOAD((s + 2 >= NSTAGE) ? s + 2 - NSTAGE : s + 2, c + 2);
            CP_COMMIT();
            asm volatile("cp.async.wait_group 2;" ::: "memory");
        } else if (c + 1 < NC) {
            asm volatile("cp.async.wait_group 1;" ::: "memory");
        } else {
            asm volatile("cp.async.wait_group 0;" ::: "memory");
        }
        __syncthreads();

        const uint32_t st = sbase + s * STAGEB;
#pragma unroll
        for (int ks = 0; ks < 2; ks++) {
            uint32_t ah[4][4], al[4][4], bh[8];
#pragma unroll
            for (int mt = 0; mt < 4; mt++) {
                const int r  = wm * 64 + mt * 16 + a_rowadd + row_in;
                const int cl = ks * 2 + a_cadd;
                const uint32_t off = r * 64 + ((cl ^ ((r >> 1) & 3)) << 4);
                ldsm_x4(ah[mt], st + 0 * TILEB + off);
                ldsm_x4(al[mt], st + 1 * TILEB + off);
            }
#pragma unroll
            for (int p = 0; p < 2; p++) {
                const int r  = wn * 32 + p * 16 + b_rowadd + row_in;
                const int cl = ks * 2 + b_cadd;
                const uint32_t off = r * 64 + ((cl ^ ((r >> 1) & 3)) << 4);
                ldsm_x4(&bh[p * 4], st + 2 * TILEB + off);
            }
#pragma unroll
            for (int mt = 0; mt < 4; mt++)
#pragma unroll
                for (int nt = 0; nt < 4; nt++) {
                    mma16816(acc[mt][nt], ah[mt], &bh[nt * 2]);
                    mma16816(acc[mt][nt], al[mt], &bh[nt * 2]);
                }
        }
        __syncthreads();
        s = (s + 1 >= NSTAGE) ? 0 : s + 1;
    }

#pragma unroll
    for (int mt = 0; mt < 4; mt++) {
#pragma unroll
        for (int nt = 0; nt < 4; nt++) {
            const int row = m0 + wm * 64 + mt * 16 + (lane >> 2);
            const int col = n0 + wn * 32 + nt * 8 + (lane & 3) * 2;
            if (SPLIT_OUT) {
                uint32_t h, l;
                split_pack2(acc[mt][nt][0], acc[mt][nt][1], h, l);
                *(uint32_t*)(Chi + (size_t)row * N + col) = h;
                *(uint32_t*)(Clo + (size_t)row * N + col) = l;
                split_pack2(acc[mt][nt][2], acc[mt][nt][3], h, l);
                *(uint32_t*)(Chi + (size_t)(row + 8) * N + col) = h;
                *(uint32_t*)(Clo + (size_t)(row + 8) * N + col) = l;
            } else {
                *(float2*)(C + (size_t)row * N + col) =
                    make_float2(acc[mt][nt][0], acc[mt][nt][1]);
                *(float2*)(C + (size_t)(row + 8) * N + col) =
                    make_float2(acc[mt][nt][2], acc[mt][nt][3]);
            }
        }
    }
}

// ---------------------------------------------------------------------------
// Tensor-core flash attention (causal). 64q x 64k tiles, Dh=64, fp16 x3.
// ---------------------------------------------------------------------------
#define AQ_HI   0
#define AQ_LO   8192
#define AKV(s)  (16384 + (s) * 32768)
#define ATTN_SMEM 81920

__global__ __launch_bounds__(128)
void attn_mma_kernel(const __half* __restrict__ qkv_hi,
                     const __half* __restrict__ qkv_lo,
                     __half* __restrict__ y_hi,
                     __half* __restrict__ y_lo)
{
    extern __shared__ char smem[];
    const uint32_t sb = smem_u32(smem);
    const int tid  = threadIdx.x;
    const int wq   = tid >> 5;
    const int lane = tid & 31;
    const int qt   = gridDim.x - 1 - blockIdx.x;
    const int h    = blockIdx.y;
    const int b    = blockIdx.z;
    const int q0   = qt * 64;

    const int lrow = tid >> 1;
    const int lcb  = (tid & 1) * 4;
    const size_t qrow_g = (size_t)(b * SEQ + q0 + lrow) * QKV_F + h * HDIM;

#pragma unroll
    for (int c = 0; c < 4; c++) {
        const int cl = lcb + c;
        const uint32_t so = lrow * 128 + ((cl ^ (lrow & 7)) << 4);
        CP_ASYNC16(sb + AQ_HI + so, qkv_hi + qrow_g + cl * 8);
        CP_ASYNC16(sb + AQ_LO + so, qkv_lo + qrow_g + cl * 8);
    }
    auto LOAD_KV = [&](int kt, int s) {
        const size_t krow_g = (size_t)(b * SEQ + kt * 64 + lrow) * QKV_F + D_MODEL + h * HDIM;
        const size_t vrow_g = krow_g + D_MODEL;
        const uint32_t base = sb + AKV(s);
#pragma unroll
        for (int c = 0; c < 4; c++) {
            const int cl = lcb + c;
            const uint32_t so = lrow * 128 + ((cl ^ (lrow & 7)) << 4);
            CP_ASYNC16(base +     0 + so, qkv_hi + krow_g + cl * 8);
            CP_ASYNC16(base +  8192 + so, qkv_lo + krow_g + cl * 8);
            CP_ASYNC16(base + 16384 + so, qkv_hi + vrow_g + cl * 8);
            CP_ASYNC16(base + 24576 + so, qkv_lo + vrow_g + cl * 8);
        }
    };

    LOAD_KV(0, 0);
    CP_COMMIT();

    const int mi     = lane >> 3;
    const int row_in = lane & 7;
    const int r0     = lane >> 2;
    const int c0     = (lane & 3) * 2;

    uint32_t qh[4][4], ql[4][4];
    float oacc[8][4];
    float m0 = -1e30f, m1 = -1e30f, l0 = 0.f, l1 = 0.f;
#pragma unroll
    for (int i = 0; i < 8; i++)
#pragma unroll
        for (int j = 0; j < 4; j++) oacc[i][j] = 0.f;

    const float LSCALE = 0.18033688f;     // 0.125 * log2(e)

    for (int kt = 0; kt <= qt; kt++) {
        const int s = kt & 1;
        if (kt < qt) {
            LOAD_KV(kt + 1, s ^ 1);
            CP_COMMIT();
            asm volatile("cp.async.wait_group 1;" ::: "memory");
        } else {
            asm volatile("cp.async.wait_group 0;" ::: "memory");
        }
        __syncthreads();

        if (kt == 0) {
#pragma unroll
            for (int ks = 0; ks < 4; ks++) {
                const int r  = wq * 16 + (mi & 1) * 8 + row_in;
                const int cl = ks * 2 + (mi >> 1);
                const uint32_t off = r * 128 + ((cl ^ (r & 7)) << 4);
                ldsm_x4(qh[ks], sb + AQ_HI + off);
                ldsm_x4(ql[ks], sb + AQ_LO + off);
            }
        }

        float sacc[8][4];
#pragma unroll
        for (int i = 0; i < 8; i++)
#pragma unroll
            for (int j = 0; j < 4; j++) sacc[i][j] = 0.f;

        const uint32_t kbase = sb + AKV(s);
#pragma unroll
        for (int ks = 0; ks < 4; ks++) {
#pragma unroll
            for (int ntp = 0; ntp < 4; ntp++) {
                uint32_t kh[4], kl[4];
                const int r  = ntp * 16 + (mi >> 1) * 8 + row_in;
                const int cl = ks * 2 + (mi & 1);
                const uint32_t off = r * 128 + ((cl ^ (r & 7)) << 4);
                ldsm_x4(kh, kbase + off);
                ldsm_x4(kl, kbase + 8192 + off);
                mma16816(sacc[ntp * 2],     qh[ks], &kh[0]);
                mma16816(sacc[ntp * 2],     qh[ks], &kl[0]);
                mma16816(sacc[ntp * 2],     ql[ks], &kh[0]);
                mma16816(sacc[ntp * 2 + 1], qh[ks], &kh[2]);
                mma16816(sacc[ntp * 2 + 1], qh[ks], &kl[2]);
                mma16816(sacc[ntp * 2 + 1], ql[ks], &kh[2]);
            }
        }

        if (kt == qt) {
            const int row_a = q0 + wq * 16 + r0;
            const int row_b = row_a + 8;
#pragma unroll
            for (int nt = 0; nt < 8; nt++) {
                const int col = q0 + nt * 8 + c0;
                if (col     > row_a) sacc[nt][0] = -1e30f;
                if (col + 1 > row_a) sacc[nt][1] = -1e30f;
                if (col     > row_b) sacc[nt][2] = -1e30f;
                if (col + 1 > row_b) sacc[nt][3] = -1e30f;
            }
        }

        float mx0 = -1e30f, mx1 = -1e30f;
#pragma unroll
        for (int nt = 0; nt < 8; nt++) {
            mx0 = fmaxf(mx0, fmaxf(sacc[nt][0], sacc[nt][1]));
            mx1 = fmaxf(mx1, fmaxf(sacc[nt][2], sacc[nt][3]));
        }
        mx0 = fmaxf(mx0, __shfl_xor_sync(0xffffffffu, mx0, 1));
        mx0 = fmaxf(mx0, __shfl_xor_sync(0xffffffffu, mx0, 2));
        mx1 = fmaxf(mx1, __shfl_xor_sync(0xffffffffu, mx1, 1));
        mx1 = fmaxf(mx1, __shfl_xor_sync(0xffffffffu, mx1, 2));
        const float mn0 = fmaxf(m0, mx0), mn1 = fmaxf(m1, mx1);
        const float al0 = ex2((m0 - mn0) * LSCALE);
        const float al1 = ex2((m1 - mn1) * LSCALE);
        m0 = mn0; m1 = mn1;

        float rs0 = 0.f, rs1 = 0.f;
#pragma unroll
        for (int nt = 0; nt < 8; nt++) {
            sacc[nt][0] = ex2((sacc[nt][0] - mn0) * LSCALE);
            sacc[nt][1] = ex2((sacc[nt][1] - mn0) * LSCALE);
            sacc[nt][2] = ex2((sacc[nt][2] - mn1) * LSCALE);
            sacc[nt][3] = ex2((sacc[nt][3] - mn1) * LSCALE);
            rs0 += sacc[nt][0] + sacc[nt][1];
            rs1 += sacc[nt][2] + sacc[nt][3];
        }
        rs0 += __shfl_xor_sync(0xffffffffu, rs0, 1);
        rs0 += __shfl_xor_sync(0xffffffffu, rs0, 2);
        rs1 += __shfl_xor_sync(0xffffffffu, rs1, 1);
        rs1 += __shfl_xor_sync(0xffffffffu, rs1, 2);
        l0 = l0 * al0 + rs0;
        l1 = l1 * al1 + rs1;
#pragma unroll
        for (int nt = 0; nt < 8; nt++) {
            oacc[nt][0] *= al0; oacc[nt][1] *= al0;
            oacc[nt][2] *= al1; oacc[nt][3] *= al1;
        }

        const uint32_t vbase = sb + AKV(s) + 16384;
#pragma unroll
        for (int kb = 0; kb < 4; kb++) {
            uint32_t ph[4], pl[4];
            split_pack2(sacc[2 * kb][0],     sacc[2 * kb][1],     ph[0], pl[0]);
            split_pack2(sacc[2 * kb][2],     sacc[2 * kb][3],     ph[1], pl[1]);
            split_pack2(sacc[2 * kb + 1][0], sacc[2 * kb + 1][1], ph[2], pl[2]);
            split_pack2(sacc[2 * kb + 1][2], sacc[2 * kb + 1][3], ph[3], pl[3]);
#pragma unroll
            for (int dp = 0; dp < 4; dp++) {
                uint32_t vh[4], vl[4];
                const int kr = kb * 16 + (mi & 1) * 8 + row_in;
                const int cl = dp * 2 + (mi >> 1);
                const uint32_t off = kr * 128 + ((cl ^ (kr & 7)) << 4);
                ldsm_x4_t(vh, vbase + off);
                ldsm_x4_t(vl, vbase + 8192 + off);
                mma16816(oacc[dp * 2],     ph, &vh[0]);
                mma16816(oacc[dp * 2],     ph, &vl[0]);
                mma16816(oacc[dp * 2],     pl, &vh[0]);
                mma16816(oacc[dp * 2 + 1], ph, &vh[2]);
                mma16816(oacc[dp * 2 + 1], ph, &vl[2]);
                mma16816(oacc[dp * 2 + 1], pl, &vh[2]);
            }
        }
        __syncthreads();
    }

    const float inv0 = 1.f / l0, inv1 = 1.f / l1;
    const int row_a = b * SEQ + q0 + wq * 16 + r0;
    const int col_b = h * HDIM + c0;
#pragma unroll
    for (int nt = 0; nt < 8; nt++) {
        uint32_t hA, lA, hB, lB;
        split_pack2(oacc[nt][0] * inv0, oacc[nt][1] * inv0, hA, lA);
        split_pack2(oacc[nt][2] * inv1, oacc[nt][3] * inv1, hB, lB);
        const size_t oA = (size_t)row_a * D_MODEL + col_b + nt * 8;
        const size_t oB = (size_t)(row_a + 8) * D_MODEL + col_b + nt * 8;
        *(uint32_t*)(y_hi + oA) = hA;
        *(uint32_t*)(y_lo + oA) = lA;
        *(uint32_t*)(y_hi + oB) = hB;
        *(uint32_t*)(y_lo + oB) = lB;
    }
}

// ---------------------------------------------------------------------------
extern "C" void kernel_launch(void* const* d_in, const int* in_sizes, int n_in,
                              void* d_out, int out_size)
{
    (void)in_sizes; (void)n_in; (void)out_size;
    const float* x      = (const float*)d_in[0];
    const float* w_qkv  = (const float*)d_in[1];
    const float* w_proj = (const float*)d_in[2];
    float* out = (float*)d_out;

    __half *qkvh, *qkvl, *xhi, *xlo, *yhi, *ylo, *wqh, *wph;
    cudaGetSymbolAddress((void**)&qkvh, g_qkv_hi);
    cudaGetSymbolAddress((void**)&qkvl, g_qkv_lo);
    cudaGetSymbolAddress((void**)&xhi, g_x_hi);
    cudaGetSymbolAddress((void**)&xlo, g_x_lo);
    cudaGetSymbolAddress((void**)&yhi, g_y_hi);
    cudaGetSymbolAddress((void**)&ylo, g_y_lo);
    cudaGetSymbolAddress((void**)&wqh, g_wqkv_h);
    cudaGetSymbolAddress((void**)&wph, g_wproj_h);

    cudaFuncSetAttribute(gemm_mma<true>,  cudaFuncAttributeMaxDynamicSharedMemorySize, GEMM_SMEM);
    cudaFuncSetAttribute(gemm_mma<false>, cudaFuncAttributeMaxDynamicSharedMemorySize, GEMM_SMEM);
    cudaFuncSetAttribute(attn_mma_kernel, cudaFuncAttributeMaxDynamicSharedMemorySize, ATTN_SMEM);

    const int nX  = MROWS * D_MODEL / 4;
    const int nWq = QKV_F * D_MODEL / 4;
    const int nWp = D_MODEL * D_MODEL / 4;

    split_fp16_kernel<<<(nX + 255) / 256, 256>>>(x, xhi, xlo, nX);
    cvt_fp16_kernel<<<(nWq + 255) / 256, 256>>>(w_qkv, wqh, nWq);
    cvt_fp16_kernel<<<(nWp + 255) / 256, 256>>>(w_proj, wph, nWp);

    gemm_mma<true><<<dim3(QKV_F / BN, MROWS / BM), 256, GEMM_SMEM>>>(
        xhi, xlo, wqh, nullptr, qkvh, qkvl, QKV_F, D_MODEL);

    attn_mma_kernel<<<dim3(SEQ / 64, NHEADS, BATCH), 128, ATTN_SMEM>>>(qkvh, qkvl, yhi, ylo);

    gemm_mma<false><<<dim3(D_MODEL / BN, MROWS / BM), 256, GEMM_SMEM>>>(
        yhi, ylo, wph, out, nullptr, nullptr, D_MODEL, D_MODEL);
}

// round 8
// speedup vs baseline: 4.2214x; 1.2045x over previous
#include <cuda_runtime.h>
#include <cuda_fp16.h>
#include <cstdint>
#include <math.h>

#define D_MODEL 1024
#define QKV_F   3072
#define NHEADS  16
#define HDIM    64
#define BATCH   4
#define SEQ     2048
#define MROWS   (BATCH * SEQ)   // 8192

// ---------------------------------------------------------------------------
// Scratch (__device__ globals; allocation-free rule)
// ---------------------------------------------------------------------------
__device__ __half g_qkv_hi[(size_t)MROWS * QKV_F];
__device__ __half g_qkv_lo[(size_t)MROWS * QKV_F];
__device__ __half g_x_hi[(size_t)MROWS * D_MODEL];
__device__ __half g_x_lo[(size_t)MROWS * D_MODEL];
__device__ __half g_y_hi[(size_t)MROWS * D_MODEL];
__device__ __half g_y_lo[(size_t)MROWS * D_MODEL];
__device__ __half g_wqkv_h[(size_t)QKV_F * D_MODEL];
__device__ __half g_wproj_h[(size_t)D_MODEL * D_MODEL];

// ---------------------------------------------------------------------------
// Helpers (base sm_103 ISA: mma.sync / ldmatrix / cp.async)
// ---------------------------------------------------------------------------
__device__ __forceinline__ uint32_t smem_u32(const void* p) {
    uint32_t a;
    asm("{ .reg .u64 t; cvta.to.shared.u64 t, %1; cvt.u32.u64 %0, t; }" : "=r"(a) : "l"(p));
    return a;
}
__device__ __forceinline__ void ldsm_x4(uint32_t* r, uint32_t addr) {
    asm volatile("ldmatrix.sync.aligned.m8n8.x4.shared.b16 {%0,%1,%2,%3}, [%4];"
        : "=r"(r[0]), "=r"(r[1]), "=r"(r[2]), "=r"(r[3]) : "r"(addr));
}
__device__ __forceinline__ void ldsm_x4_t(uint32_t* r, uint32_t addr) {
    asm volatile("ldmatrix.sync.aligned.m8n8.x4.trans.shared.b16 {%0,%1,%2,%3}, [%4];"
        : "=r"(r[0]), "=r"(r[1]), "=r"(r[2]), "=r"(r[3]) : "r"(addr));
}
// fp16 inputs, fp32 accum
__device__ __forceinline__ void mma16816(float* d, const uint32_t* a, const uint32_t* b) {
    asm volatile("mma.sync.aligned.m16n8k16.row.col.f32.f16.f16.f32 "
        "{%0,%1,%2,%3}, {%4,%5,%6,%7}, {%8,%9}, {%0,%1,%2,%3};"
        : "+f"(d[0]), "+f"(d[1]), "+f"(d[2]), "+f"(d[3])
        : "r"(a[0]), "r"(a[1]), "r"(a[2]), "r"(a[3]), "r"(b[0]), "r"(b[1]));
}
#define CP_ASYNC16(dst, src) \
    asm volatile("cp.async.cg.shared.global [%0], [%1], 16;" :: "r"(dst), "l"(src) : "memory")
#define CP_COMMIT() asm volatile("cp.async.commit_group;" ::: "memory")

__device__ __forceinline__ float ex2(float x) {
    float y; asm("ex2.approx.f32 %0, %1;" : "=f"(y) : "f"(x)); return y;
}
// split x0,x1 into packed fp16x2 hi & lo planes (x0 in low half)
__device__ __forceinline__ void split_pack2(float x0, float x1, uint32_t& hi, uint32_t& lo) {
    __half h0 = __float2half_rn(x0), h1 = __float2half_rn(x1);
    __half l0 = __float2half_rn(x0 - __half2float(h0));
    __half l1 = __float2half_rn(x1 - __half2float(h1));
    __half2 H = __halves2half2(h0, h1), L = __halves2half2(l0, l1);
    hi = *reinterpret_cast<uint32_t*>(&H);
    lo = *reinterpret_cast<uint32_t*>(&L);
}

// ---------------------------------------------------------------------------
// fp32 -> (fp16 hi, fp16 lo) elementwise split
// ---------------------------------------------------------------------------
__global__ void split_fp16_kernel(const float* __restrict__ in,
                                  __half* __restrict__ hi,
                                  __half* __restrict__ lo, int n4)
{
    int i = blockIdx.x * blockDim.x + threadIdx.x;
    if (i >= n4) return;
    float4 v = ((const float4*)in)[i];
    uint32_t h01, l01, h23, l23;
    split_pack2(v.x, v.y, h01, l01);
    split_pack2(v.z, v.w, h23, l23);
    uint32_t* hp = (uint32_t*)(hi + (size_t)i * 4);
    uint32_t* lp = (uint32_t*)(lo + (size_t)i * 4);
    hp[0] = h01; hp[1] = h23;
    lp[0] = l01; lp[1] = l23;
}

// fp32 -> fp16 (hi only, for weights)
__global__ void cvt_fp16_kernel(const float* __restrict__ in,
                                __half* __restrict__ hi, int n4)
{
    int i = blockIdx.x * blockDim.x + threadIdx.x;
    if (i >= n4) return;
    float4 v = ((const float4*)in)[i];
    __half2 a = __halves2half2(__float2half_rn(v.x), __float2half_rn(v.y));
    __half2 b = __halves2half2(__float2half_rn(v.z), __float2half_rn(v.w));
    uint32_t* hp = (uint32_t*)(hi + (size_t)i * 4);
    hp[0] = *reinterpret_cast<uint32_t*>(&a);
    hp[1] = *reinterpret_cast<uint32_t*>(&b);
}

// ---------------------------------------------------------------------------
// mma.sync GEMM: C[M,N] = A[M,K] @ W[N,K]^T  (fp16x2: (Ah+Al)*Wh, fp32 accum)
// CTA 128x128, BK=32, 256 threads, warp tile 64x32, 3-stage cp.async.
// ---------------------------------------------------------------------------
#define BM 128
#define BN 128
#define BK 32
#define NSTAGE 3
#define TILEB  (BM * BK * 2)
#define STAGEB (3 * TILEB)            // 24 KB
#define GEMM_SMEM (NSTAGE * STAGEB)   // 72 KB

template<bool SPLIT_OUT>
__global__ __launch_bounds__(256, 2)
void gemm_mma(const __half* __restrict__ Ahi, const __half* __restrict__ Alo,
              const __half* __restrict__ Wh,
              float* __restrict__ C,
              __half* __restrict__ Chi, __half* __restrict__ Clo,
              int N, int K)
{
    extern __shared__ char smem[];
    const uint32_t sbase = smem_u32(smem);
    const int tid  = threadIdx.x;
    const int wid  = tid >> 5;
    const int lane = tid & 31;
    const int wm   = wid & 1;
    const int wn   = wid >> 1;
    const int m0   = blockIdx.y * BM;
    const int n0   = blockIdx.x * BN;

    const int lrow = tid >> 1;
    const int lc0  = (tid & 1) * 2;
    const int lswz = (lrow >> 1) & 3;

    const __half* srcs[3];
    srcs[0] = Ahi + (size_t)(m0 + lrow) * K;
    srcs[1] = Alo + (size_t)(m0 + lrow) * K;
    srcs[2] = Wh  + (size_t)(n0 + lrow) * K;

    auto LOAD = [&](int s, int c) {
#pragma unroll
        for (int a = 0; a < 3; a++) {
#pragma unroll
            for (int j = 0; j < 2; j++) {
                const int cl = lc0 + j;
                const uint32_t dst = sbase + s * STAGEB + a * TILEB
                                   + lrow * 64 + ((cl ^ lswz) << 4);
                CP_ASYNC16(dst, srcs[a] + (size_t)c * BK + cl * 8);
            }
        }
    };

    float acc[4][4][4];
#pragma unroll
    for (int i = 0; i < 4; i++)
#pragma unroll
        for (int j = 0; j < 4; j++)
#pragma unroll
            for (int k = 0; k < 4; k++) acc[i][j][k] = 0.f;

    const int NC = K / BK;
    LOAD(0, 0);
    CP_COMMIT();
    LOAD(1, 1);
    CP_COMMIT();

    const int mi     = lane >> 3;
    const int row_in = lane & 7;
    const int a_rowadd = (mi & 1) * 8;
    const int a_cadd   = mi >> 1;
    const int b_rowadd = (mi >> 1) * 8;
    const int b_cadd   = mi & 1;

    int s = 0;
    for (int c = 0; c < NC; c++) {
        if (c + 2 < NC) {
            LOAD((s + 2 >= NSTAGE) ? s + 2 - NSTAGE : s + 2, c + 2);
            CP_COMMIT();
            asm volatile("cp.async.wait_group 2;" ::: "memory");
        } else if (c + 1 < NC) {
            asm volatile("cp.async.wait_group 1;" ::: "memory");
        } else {
            asm volatile("cp.async.wait_group 0;" ::: "memory");
        }
        __syncthreads();

        const uint32_t st = sbase + s * STAGEB;
#pragma unroll
        for (int ks = 0; ks < 2; ks++) {
            uint32_t ah[4][4], al[4][4], bh[8];
#pragma unroll
            for (int mt = 0; mt < 4; mt++) {
                const int r  = wm * 64 + mt * 16 + a_rowadd + row_in;
                const int cl = ks * 2 + a_cadd;
                const uint32_t off = r * 64 + ((cl ^ ((r >> 1) & 3)) << 4);
                ldsm_x4(ah[mt], st + 0 * TILEB + off);
                ldsm_x4(al[mt], st + 1 * TILEB + off);
            }
#pragma unroll
            for (int p = 0; p < 2; p++) {
                const int r  = wn * 32 + p * 16 + b_rowadd + row_in;
                const int cl = ks * 2 + b_cadd;
                const uint32_t off = r * 64 + ((cl ^ ((r >> 1) & 3)) << 4);
                ldsm_x4(&bh[p * 4], st + 2 * TILEB + off);
            }
#pragma unroll
            for (int mt = 0; mt < 4; mt++)
#pragma unroll
                for (int nt = 0; nt < 4; nt++) {
                    mma16816(acc[mt][nt], ah[mt], &bh[nt * 2]);
                    mma16816(acc[mt][nt], al[mt], &bh[nt * 2]);
                }
        }
        __syncthreads();
        s = (s + 1 >= NSTAGE) ? 0 : s + 1;
    }

#pragma unroll
    for (int mt = 0; mt < 4; mt++) {
#pragma unroll
        for (int nt = 0; nt < 4; nt++) {
            const int row = m0 + wm * 64 + mt * 16 + (lane >> 2);
            const int col = n0 + wn * 32 + nt * 8 + (lane & 3) * 2;
            if (SPLIT_OUT) {
                uint32_t h, l;
                split_pack2(acc[mt][nt][0], acc[mt][nt][1], h, l);
                *(uint32_t*)(Chi + (size_t)row * N + col) = h;
                *(uint32_t*)(Clo + (size_t)row * N + col) = l;
                split_pack2(acc[mt][nt][2], acc[mt][nt][3], h, l);
                *(uint32_t*)(Chi + (size_t)(row + 8) * N + col) = h;
                *(uint32_t*)(Clo + (size_t)(row + 8) * N + col) = l;
            } else {
                *(float2*)(C + (size_t)row * N + col) =
                    make_float2(acc[mt][nt][0], acc[mt][nt][1]);
                *(float2*)(C + (size_t)(row + 8) * N + col) =
                    make_float2(acc[mt][nt][2], acc[mt][nt][3]);
            }
        }
    }
}

// ---------------------------------------------------------------------------
// Tensor-core flash attention (causal). 64q x 64k tiles, Dh=64.
// S = (Qh+Ql)*Kh ; O = (Ph+Pl)*Vh  (K,V single fp16; Q,P exact via hi/lo)
// Smem: Q hi/lo + double-buffered {Khi,Vhi}. 48 KB total.
// ---------------------------------------------------------------------------
#define AQ_HI   0
#define AQ_LO   8192
#define AKV(s)  (16384 + (s) * 16384)   // Khi at +0, Vhi at +8192
#define ATTN_SMEM 49152

__global__ __launch_bounds__(128)
void attn_mma_kernel(const __half* __restrict__ qkv_hi,
                     const __half* __restrict__ qkv_lo,
                     __half* __restrict__ y_hi,
                     __half* __restrict__ y_lo)
{
    extern __shared__ char smem[];
    const uint32_t sb = smem_u32(smem);
    const int tid  = threadIdx.x;
    const int wq   = tid >> 5;
    const int lane = tid & 31;
    const int qt   = gridDim.x - 1 - blockIdx.x;
    const int h    = blockIdx.y;
    const int b    = blockIdx.z;
    const int q0   = qt * 64;

    const int lrow = tid >> 1;
    const int lcb  = (tid & 1) * 4;
    const size_t qrow_g = (size_t)(b * SEQ + q0 + lrow) * QKV_F + h * HDIM;

#pragma unroll
    for (int c = 0; c < 4; c++) {
        const int cl = lcb + c;
        const uint32_t so = lrow * 128 + ((cl ^ (lrow & 7)) << 4);
        CP_ASYNC16(sb + AQ_HI + so, qkv_hi + qrow_g + cl * 8);
        CP_ASYNC16(sb + AQ_LO + so, qkv_lo + qrow_g + cl * 8);
    }
    auto LOAD_KV = [&](int kt, int s) {
        const size_t krow_g = (size_t)(b * SEQ + kt * 64 + lrow) * QKV_F + D_MODEL + h * HDIM;
        const size_t vrow_g = krow_g + D_MODEL;
        const uint32_t base = sb + AKV(s);
#pragma unroll
        for (int c = 0; c < 4; c++) {
            const int cl = lcb + c;
            const uint32_t so = lrow * 128 + ((cl ^ (lrow & 7)) << 4);
            CP_ASYNC16(base +    0 + so, qkv_hi + krow_g + cl * 8);
            CP_ASYNC16(base + 8192 + so, qkv_hi + vrow_g + cl * 8);
        }
    };

    LOAD_KV(0, 0);
    CP_COMMIT();

    const int mi     = lane >> 3;
    const int row_in = lane & 7;
    const int r0     = lane >> 2;
    const int c0     = (lane & 3) * 2;

    uint32_t qh[4][4], ql[4][4];
    float oacc[8][4];
    float m0 = -1e30f, m1 = -1e30f, l0 = 0.f, l1 = 0.f;
#pragma unroll
    for (int i = 0; i < 8; i++)
#pragma unroll
        for (int j = 0; j < 4; j++) oacc[i][j] = 0.f;

    const float LSCALE = 0.18033688f;     // 0.125 * log2(e)

    for (int kt = 0; kt <= qt; kt++) {
        const int s = kt & 1;
        if (kt < qt) {
            LOAD_KV(kt + 1, s ^ 1);
            CP_COMMIT();
            asm volatile("cp.async.wait_group 1;" ::: "memory");
        } else {
            asm volatile("cp.async.wait_group 0;" ::: "memory");
        }
        __syncthreads();

        if (kt == 0) {
#pragma unroll
            for (int ks = 0; ks < 4; ks++) {
                const int r  = wq * 16 + (mi & 1) * 8 + row_in;
                const int cl = ks * 2 + (mi >> 1);
                const uint32_t off = r * 128 + ((cl ^ (r & 7)) << 4);
                ldsm_x4(qh[ks], sb + AQ_HI + off);
                ldsm_x4(ql[ks], sb + AQ_LO + off);
            }
        }

        float sacc[8][4];
#pragma unroll
        for (int i = 0; i < 8; i++)
#pragma unroll
            for (int j = 0; j < 4; j++) sacc[i][j] = 0.f;

        const uint32_t kbase = sb + AKV(s);
#pragma unroll
        for (int ks = 0; ks < 4; ks++) {
#pragma unroll
            for (int ntp = 0; ntp < 4; ntp++) {
                uint32_t kh[4];
                const int r  = ntp * 16 + (mi >> 1) * 8 + row_in;
                const int cl = ks * 2 + (mi & 1);
                const uint32_t off = r * 128 + ((cl ^ (r & 7)) << 4);
                ldsm_x4(kh, kbase + off);
                mma16816(sacc[ntp * 2],     qh[ks], &kh[0]);
                mma16816(sacc[ntp * 2],     ql[ks], &kh[0]);
                mma16816(sacc[ntp * 2 + 1], qh[ks], &kh[2]);
                mma16816(sacc[ntp * 2 + 1], ql[ks], &kh[2]);
            }
        }

        if (kt == qt) {
            const int row_a = q0 + wq * 16 + r0;
            const int row_b = row_a + 8;
#pragma unroll
            for (int nt = 0; nt < 8; nt++) {
                const int col = q0 + nt * 8 + c0;
                if (col     > row_a) sacc[nt][0] = -1e30f;
                if (col + 1 > row_a) sacc[nt][1] = -1e30f;
                if (col     > row_b) sacc[nt][2] = -1e30f;
                if (col + 1 > row_b) sacc[nt][3] = -1e30f;
            }
        }

        float mx0 = -1e30f, mx1 = -1e30f;
#pragma unroll
        for (int nt = 0; nt < 8; nt++) {
            mx0 = fmaxf(mx0, fmaxf(sacc[nt][0], sacc[nt][1]));
            mx1 = fmaxf(mx1, fmaxf(sacc[nt][2], sacc[nt][3]));
        }
        mx0 = fmaxf(mx0, __shfl_xor_sync(0xffffffffu, mx0, 1));
        mx0 = fmaxf(mx0, __shfl_xor_sync(0xffffffffu, mx0, 2));
        mx1 = fmaxf(mx1, __shfl_xor_sync(0xffffffffu, mx1, 1));
        mx1 = fmaxf(mx1, __shfl_xor_sync(0xffffffffu, mx1, 2));
        const float mn0 = fmaxf(m0, mx0), mn1 = fmaxf(m1, mx1);
        const float al0 = ex2((m0 - mn0) * LSCALE);
        const float al1 = ex2((m1 - mn1) * LSCALE);
        m0 = mn0; m1 = mn1;

        float rs0 = 0.f, rs1 = 0.f;
#pragma unroll
        for (int nt = 0; nt < 8; nt++) {
            sacc[nt][0] = ex2((sacc[nt][0] - mn0) * LSCALE);
            sacc[nt][1] = ex2((sacc[nt][1] - mn0) * LSCALE);
            sacc[nt][2] = ex2((sacc[nt][2] - mn1) * LSCALE);
            sacc[nt][3] = ex2((sacc[nt][3] - mn1) * LSCALE);
            rs0 += sacc[nt][0] + sacc[nt][1];
            rs1 += sacc[nt][2] + sacc[nt][3];
        }
        rs0 += __shfl_xor_sync(0xffffffffu, rs0, 1);
        rs0 += __shfl_xor_sync(0xffffffffu, rs0, 2);
        rs1 += __shfl_xor_sync(0xffffffffu, rs1, 1);
        rs1 += __shfl_xor_sync(0xffffffffu, rs1, 2);
        l0 = l0 * al0 + rs0;
        l1 = l1 * al1 + rs1;
#pragma unroll
        for (int nt = 0; nt < 8; nt++) {
            oacc[nt][0] *= al0; oacc[nt][1] *= al0;
            oacc[nt][2] *= al1; oacc[nt][3] *= al1;
        }

        const uint32_t vbase = sb + AKV(s) + 8192;
#pragma unroll
        for (int kb = 0; kb < 4; kb++) {
            uint32_t ph[4], pl[4];
            split_pack2(sacc[2 * kb][0],     sacc[2 * kb][1],     ph[0], pl[0]);
            split_pack2(sacc[2 * kb][2],     sacc[2 * kb][3],     ph[1], pl[1]);
            split_pack2(sacc[2 * kb + 1][0], sacc[2 * kb + 1][1], ph[2], pl[2]);
            split_pack2(sacc[2 * kb + 1][2], sacc[2 * kb + 1][3], ph[3], pl[3]);
#pragma unroll
            for (int dp = 0; dp < 4; dp++) {
                uint32_t vh[4];
                const int kr = kb * 16 + (mi & 1) * 8 + row_in;
                const int cl = dp * 2 + (mi >> 1);
                const uint32_t off = kr * 128 + ((cl ^ (kr & 7)) << 4);
                ldsm_x4_t(vh, vbase + off);
                mma16816(oacc[dp * 2],     ph, &vh[0]);
                mma16816(oacc[dp * 2],     pl, &vh[0]);
                mma16816(oacc[dp * 2 + 1], ph, &vh[2]);
                mma16816(oacc[dp * 2 + 1], pl, &vh[2]);
            }
        }
        __syncthreads();
    }

    const float inv0 = 1.f / l0, inv1 = 1.f / l1;
    const int row_a = b * SEQ + q0 + wq * 16 + r0;
    const int col_b = h * HDIM + c0;
#pragma unroll
    for (int nt = 0; nt < 8; nt++) {
        uint32_t hA, lA, hB, lB;
        split_pack2(oacc[nt][0] * inv0, oacc[nt][1] * inv0, hA, lA);
        split_pack2(oacc[nt][2] * inv1, oacc[nt][3] * inv1, hB, lB);
        const size_t oA = (size_t)row_a * D_MODEL + col_b + nt * 8;
        const size_t oB = (size_t)(row_a + 8) * D_MODEL + col_b + nt * 8;
        *(uint32_t*)(y_hi + oA) = hA;
        *(uint32_t*)(y_lo + oA) = lA;
        *(uint32_t*)(y_hi + oB) = hB;
        *(uint32_t*)(y_lo + oB) = lB;
    }
}

// ---------------------------------------------------------------------------
extern "C" void kernel_launch(void* const* d_in, const int* in_sizes, int n_in,
                              void* d_out, int out_size)
{
    (void)in_sizes; (void)n_in; (void)out_size;
    const float* x      = (const float*)d_in[0];
    const float* w_qkv  = (const float*)d_in[1];
    const float* w_proj = (const float*)d_in[2];
    float* out = (float*)d_out;

    __half *qkvh, *qkvl, *xhi, *xlo, *yhi, *ylo, *wqh, *wph;
    cudaGetSymbolAddress((void**)&qkvh, g_qkv_hi);
    cudaGetSymbolAddress((void**)&qkvl, g_qkv_lo);
    cudaGetSymbolAddress((void**)&xhi, g_x_hi);
    cudaGetSymbolAddress((void**)&xlo, g_x_lo);
    cudaGetSymbolAddress((void**)&yhi, g_y_hi);
    cudaGetSymbolAddress((void**)&ylo, g_y_lo);
    cudaGetSymbolAddress((void**)&wqh, g_wqkv_h);
    cudaGetSymbolAddress((void**)&wph, g_wproj_h);

    cudaFuncSetAttribute(gemm_mma<true>,  cudaFuncAttributeMaxDynamicSharedMemorySize, GEMM_SMEM);
    cudaFuncSetAttribute(gemm_mma<false>, cudaFuncAttributeMaxDynamicSharedMemorySize, GEMM_SMEM);
    cudaFuncSetAttribute(attn_mma_kernel, cudaFuncAttributeMaxDynamicSharedMemorySize, ATTN_SMEM);

    const int nX  = MROWS * D_MODEL / 4;
    const int nWq = QKV_F * D_MODEL / 4;
    const int nWp = D_MODEL * D_MODEL / 4;

    split_fp16_kernel<<<(nX + 255) / 256, 256>>>(x, xhi, xlo, nX);
    cvt_fp16_kernel<<<(nWq + 255) / 256, 256>>>(w_qkv, wqh, nWq);
    cvt_fp16_kernel<<<(nWp + 255) / 256, 256>>>(w_proj, wph, nWp);

    gemm_mma<true><<<dim3(QKV_F / BN, MROWS / BM), 256, GEMM_SMEM>>>(
        xhi, xlo, wqh, nullptr, qkvh, qkvl, QKV_F, D_MODEL);

    attn_mma_kernel<<<dim3(SEQ / 64, NHEADS, BATCH), 128, ATTN_SMEM>>>(qkvh, qkvl, yhi, ylo);

    gemm_mma<false><<<dim3(D_MODEL / BN, MROWS / BM), 256, GEMM_SMEM>>>(
        yhi, ylo, wph, out, nullptr, nullptr, D_MODEL, D_MODEL);
}

// round 9
// speedup vs baseline: 5.2976x; 1.2549x over previous
#include <cuda_runtime.h>
#include <cuda_fp16.h>
#include <cstdint>
#include <math.h>

#define D_MODEL 1024
#define QKV_F   3072
#define NHEADS  16
#define HDIM    64
#define BATCH   4
#define SEQ     2048
#define MROWS   (BATCH * SEQ)   // 8192

// ---------------------------------------------------------------------------
// Scratch (__device__ globals; allocation-free rule)
// ---------------------------------------------------------------------------
__device__ __half g_qkv_hi[(size_t)MROWS * QKV_F];
__device__ __half g_qkv_lo[(size_t)MROWS * QKV_F];
__device__ __half g_x_h[(size_t)MROWS * D_MODEL];
__device__ __half g_y_h[(size_t)MROWS * D_MODEL];
__device__ __half g_wqkv_h[(size_t)QKV_F * D_MODEL];
__device__ __half g_wproj_h[(size_t)D_MODEL * D_MODEL];

// ---------------------------------------------------------------------------
// Helpers (base sm_103 ISA: mma.sync / ldmatrix / cp.async)
// ---------------------------------------------------------------------------
__device__ __forceinline__ uint32_t smem_u32(const void* p) {
    uint32_t a;
    asm("{ .reg .u64 t; cvta.to.shared.u64 t, %1; cvt.u32.u64 %0, t; }" : "=r"(a) : "l"(p));
    return a;
}
__device__ __forceinline__ void ldsm_x4(uint32_t* r, uint32_t addr) {
    asm volatile("ldmatrix.sync.aligned.m8n8.x4.shared.b16 {%0,%1,%2,%3}, [%4];"
        : "=r"(r[0]), "=r"(r[1]), "=r"(r[2]), "=r"(r[3]) : "r"(addr));
}
__device__ __forceinline__ void ldsm_x4_t(uint32_t* r, uint32_t addr) {
    asm volatile("ldmatrix.sync.aligned.m8n8.x4.trans.shared.b16 {%0,%1,%2,%3}, [%4];"
        : "=r"(r[0]), "=r"(r[1]), "=r"(r[2]), "=r"(r[3]) : "r"(addr));
}
// fp16 inputs, fp32 accum
__device__ __forceinline__ void mma16816(float* d, const uint32_t* a, const uint32_t* b) {
    asm volatile("mma.sync.aligned.m16n8k16.row.col.f32.f16.f16.f32 "
        "{%0,%1,%2,%3}, {%4,%5,%6,%7}, {%8,%9}, {%0,%1,%2,%3};"
        : "+f"(d[0]), "+f"(d[1]), "+f"(d[2]), "+f"(d[3])
        : "r"(a[0]), "r"(a[1]), "r"(a[2]), "r"(a[3]), "r"(b[0]), "r"(b[1]));
}
#define CP_ASYNC16(dst, src) \
    asm volatile("cp.async.cg.shared.global [%0], [%1], 16;" :: "r"(dst), "l"(src) : "memory")
#define CP_COMMIT() asm volatile("cp.async.commit_group;" ::: "memory")

__device__ __forceinline__ float ex2(float x) {
    float y; asm("ex2.approx.f32 %0, %1;" : "=f"(y) : "f"(x)); return y;
}
// split x0,x1 into packed fp16x2 hi & lo planes (x0 in low half)
__device__ __forceinline__ void split_pack2(float x0, float x1, uint32_t& hi, uint32_t& lo) {
    __half h0 = __float2half_rn(x0), h1 = __float2half_rn(x1);
    __half l0 = __float2half_rn(x0 - __half2float(h0));
    __half l1 = __float2half_rn(x1 - __half2float(h1));
    __half2 H = __halves2half2(h0, h1), L = __halves2half2(l0, l1);
    hi = *reinterpret_cast<uint32_t*>(&H);
    lo = *reinterpret_cast<uint32_t*>(&L);
}
__device__ __forceinline__ uint32_t pack2(float x0, float x1) {
    __half2 H = __halves2half2(__float2half_rn(x0), __float2half_rn(x1));
    return *reinterpret_cast<uint32_t*>(&H);
}

// ---------------------------------------------------------------------------
// fp32 -> fp16 convert
// ---------------------------------------------------------------------------
__global__ void cvt_fp16_kernel(const float* __restrict__ in,
                                __half* __restrict__ hi, int n4)
{
    int i = blockIdx.x * blockDim.x + threadIdx.x;
    if (i >= n4) return;
    float4 v = ((const float4*)in)[i];
    uint32_t* hp = (uint32_t*)(hi + (size_t)i * 4);
    hp[0] = pack2(v.x, v.y);
    hp[1] = pack2(v.z, v.w);
}

// ---------------------------------------------------------------------------
// mma.sync GEMM: C[M,N] = A[M,K] @ W[N,K]^T  (fp16 x1, fp32 accum)
// CTA 128x128, BK=32, 256 threads, warp tile 64x32, 3-stage cp.async.
// Planes per stage: A, W (16 KB). 2 CTAs/SM.
// ---------------------------------------------------------------------------
#define BM 128
#define BN 128
#define BK 32
#define NSTAGE 3
#define TILEB  (BM * BK * 2)
#define STAGEB (2 * TILEB)            // 16 KB
#define GEMM_SMEM (NSTAGE * STAGEB)   // 48 KB

template<bool SPLIT_OUT>
__global__ __launch_bounds__(256, 2)
void gemm_mma(const __half* __restrict__ A,
              const __half* __restrict__ Wh,
              float* __restrict__ C,
              __half* __restrict__ Chi, __half* __restrict__ Clo,
              int N, int K)
{
    extern __shared__ char smem[];
    const uint32_t sbase = smem_u32(smem);
    const int tid  = threadIdx.x;
    const int wid  = tid >> 5;
    const int lane = tid & 31;
    const int wm   = wid & 1;
    const int wn   = wid >> 1;
    const int m0   = blockIdx.y * BM;
    const int n0   = blockIdx.x * BN;

    const int lrow = tid >> 1;
    const int lc0  = (tid & 1) * 2;
    const int lswz = (lrow >> 1) & 3;

    const __half* srcs[2];
    srcs[0] = A  + (size_t)(m0 + lrow) * K;
    srcs[1] = Wh + (size_t)(n0 + lrow) * K;

    auto LOAD = [&](int s, int c) {
#pragma unroll
        for (int a = 0; a < 2; a++) {
#pragma unroll
            for (int j = 0; j < 2; j++) {
                const int cl = lc0 + j;
                const uint32_t dst = sbase + s * STAGEB + a * TILEB
                                   + lrow * 64 + ((cl ^ lswz) << 4);
                CP_ASYNC16(dst, srcs[a] + (size_t)c * BK + cl * 8);
            }
        }
    };

    float acc[4][4][4];
#pragma unroll
    for (int i = 0; i < 4; i++)
#pragma unroll
        for (int j = 0; j < 4; j++)
#pragma unroll
            for (int k = 0; k < 4; k++) acc[i][j][k] = 0.f;

    const int NC = K / BK;
    LOAD(0, 0);
    CP_COMMIT();
    LOAD(1, 1);
    CP_COMMIT();

    const int mi     = lane >> 3;
    const int row_in = lane & 7;
    const int a_rowadd = (mi & 1) * 8;
    const int a_cadd   = mi >> 1;
    const int b_rowadd = (mi >> 1) * 8;
    const int b_cadd   = mi & 1;

    int s = 0;
    for (int c = 0; c < NC; c++) {
        if (c + 2 < NC) {
            LOAD((s + 2 >= NSTAGE) ? s + 2 - NSTAGE : s + 2, c + 2);
            CP_COMMIT();
            asm volatile("cp.async.wait_group 2;" ::: "memory");
        } else if (c + 1 < NC) {
            asm volatile("cp.async.wait_group 1;" ::: "memory");
        } else {
            asm volatile("cp.async.wait_group 0;" ::: "memory");
        }
        __syncthreads();

        const uint32_t st = sbase + s * STAGEB;
#pragma unroll
        for (int ks = 0; ks < 2; ks++) {
            uint32_t ah[4][4], bh[8];
#pragma unroll
            for (int mt = 0; mt < 4; mt++) {
                const int r  = wm * 64 + mt * 16 + a_rowadd + row_in;
                const int cl = ks * 2 + a_cadd;
                const uint32_t off = r * 64 + ((cl ^ ((r >> 1) & 3)) << 4);
                ldsm_x4(ah[mt], st + 0 * TILEB + off);
            }
#pragma unroll
            for (int p = 0; p < 2; p++) {
                const int r  = wn * 32 + p * 16 + b_rowadd + row_in;
                const int cl = ks * 2 + b_cadd;
                const uint32_t off = r * 64 + ((cl ^ ((r >> 1) & 3)) << 4);
                ldsm_x4(&bh[p * 4], st + 1 * TILEB + off);
            }
#pragma unroll
            for (int mt = 0; mt < 4; mt++)
#pragma unroll
                for (int nt = 0; nt < 4; nt++)
                    mma16816(acc[mt][nt], ah[mt], &bh[nt * 2]);
        }
        __syncthreads();
        s = (s + 1 >= NSTAGE) ? 0 : s + 1;
    }

#pragma unroll
    for (int mt = 0; mt < 4; mt++) {
#pragma unroll
        for (int nt = 0; nt < 4; nt++) {
            const int row = m0 + wm * 64 + mt * 16 + (lane >> 2);
            const int col = n0 + wn * 32 + nt * 8 + (lane & 3) * 2;
            if (SPLIT_OUT) {
                uint32_t h, l;
                split_pack2(acc[mt][nt][0], acc[mt][nt][1], h, l);
                *(uint32_t*)(Chi + (size_t)row * N + col) = h;
                *(uint32_t*)(Clo + (size_t)row * N + col) = l;
                split_pack2(acc[mt][nt][2], acc[mt][nt][3], h, l);
                *(uint32_t*)(Chi + (size_t)(row + 8) * N + col) = h;
                *(uint32_t*)(Clo + (size_t)(row + 8) * N + col) = l;
            } else {
                *(float2*)(C + (size_t)row * N + col) =
                    make_float2(acc[mt][nt][0], acc[mt][nt][1]);
                *(float2*)(C + (size_t)(row + 8) * N + col) =
                    make_float2(acc[mt][nt][2], acc[mt][nt][3]);
            }
        }
    }
}

// ---------------------------------------------------------------------------
// Tensor-core flash attention (causal). 64q x 64k tiles, Dh=64.
// S = (Qh+Ql)*Kh ; O = (Ph+Pl)*Vh. y written as single fp16.
// Smem: Q hi/lo + double-buffered {Khi,Vhi}. 48 KB total.
// ---------------------------------------------------------------------------
#define AQ_HI   0
#define AQ_LO   8192
#define AKV(s)  (16384 + (s) * 16384)   // Khi at +0, Vhi at +8192
#define ATTN_SMEM 49152

__global__ __launch_bounds__(128)
void attn_mma_kernel(const __half* __restrict__ qkv_hi,
                     const __half* __restrict__ qkv_lo,
                     __half* __restrict__ y_h)
{
    extern __shared__ char smem[];
    const uint32_t sb = smem_u32(smem);
    const int tid  = threadIdx.x;
    const int wq   = tid >> 5;
    const int lane = tid & 31;
    const int qt   = gridDim.x - 1 - blockIdx.x;
    const int h    = blockIdx.y;
    const int b    = blockIdx.z;
    const int q0   = qt * 64;

    const int lrow = tid >> 1;
    const int lcb  = (tid & 1) * 4;
    const size_t qrow_g = (size_t)(b * SEQ + q0 + lrow) * QKV_F + h * HDIM;

#pragma unroll
    for (int c = 0; c < 4; c++) {
        const int cl = lcb + c;
        const uint32_t so = lrow * 128 + ((cl ^ (lrow & 7)) << 4);
        CP_ASYNC16(sb + AQ_HI + so, qkv_hi + qrow_g + cl * 8);
        CP_ASYNC16(sb + AQ_LO + so, qkv_lo + qrow_g + cl * 8);
    }
    auto LOAD_KV = [&](int kt, int s) {
        const size_t krow_g = (size_t)(b * SEQ + kt * 64 + lrow) * QKV_F + D_MODEL + h * HDIM;
        const size_t vrow_g = krow_g + D_MODEL;
        const uint32_t base = sb + AKV(s);
#pragma unroll
        for (int c = 0; c < 4; c++) {
            const int cl = lcb + c;
            const uint32_t so = lrow * 128 + ((cl ^ (lrow & 7)) << 4);
            CP_ASYNC16(base +    0 + so, qkv_hi + krow_g + cl * 8);
            CP_ASYNC16(base + 8192 + so, qkv_hi + vrow_g + cl * 8);
        }
    };

    LOAD_KV(0, 0);
    CP_COMMIT();

    const int mi     = lane >> 3;
    const int row_in = lane & 7;
    const int r0     = lane >> 2;
    const int c0     = (lane & 3) * 2;

    uint32_t qh[4][4], ql[4][4];
    float oacc[8][4];
    float m0 = -1e30f, m1 = -1e30f, l0 = 0.f, l1 = 0.f;
#pragma unroll
    for (int i = 0; i < 8; i++)
#pragma unroll
        for (int j = 0; j < 4; j++) oacc[i][j] = 0.f;

    const float LSCALE = 0.18033688f;     // 0.125 * log2(e)

    for (int kt = 0; kt <= qt; kt++) {
        const int s = kt & 1;
        if (kt < qt) {
            LOAD_KV(kt + 1, s ^ 1);
            CP_COMMIT();
            asm volatile("cp.async.wait_group 1;" ::: "memory");
        } else {
            asm volatile("cp.async.wait_group 0;" ::: "memory");
        }
        __syncthreads();

        if (kt == 0) {
#pragma unroll
            for (int ks = 0; ks < 4; ks++) {
                const int r  = wq * 16 + (mi & 1) * 8 + row_in;
                const int cl = ks * 2 + (mi >> 1);
                const uint32_t off = r * 128 + ((cl ^ (r & 7)) << 4);
                ldsm_x4(qh[ks], sb + AQ_HI + off);
                ldsm_x4(ql[ks], sb + AQ_LO + off);
            }
        }

        float sacc[8][4];
#pragma unroll
        for (int i = 0; i < 8; i++)
#pragma unroll
            for (int j = 0; j < 4; j++) sacc[i][j] = 0.f;

        const uint32_t kbase = sb + AKV(s);
#pragma unroll
        for (int ks = 0; ks < 4; ks++) {
#pragma unroll
            for (int ntp = 0; ntp < 4; ntp++) {
                uint32_t kh[4];
                const int r  = ntp * 16 + (mi >> 1) * 8 + row_in;
                const int cl = ks * 2 + (mi & 1);
                const uint32_t off = r * 128 + ((cl ^ (r & 7)) << 4);
                ldsm_x4(kh, kbase + off);
                mma16816(sacc[ntp * 2],     qh[ks], &kh[0]);
                mma16816(sacc[ntp * 2],     ql[ks], &kh[0]);
                mma16816(sacc[ntp * 2 + 1], qh[ks], &kh[2]);
                mma16816(sacc[ntp * 2 + 1], ql[ks], &kh[2]);
            }
        }

        if (kt == qt) {
            const int row_a = q0 + wq * 16 + r0;
            const int row_b = row_a + 8;
#pragma unroll
            for (int nt = 0; nt < 8; nt++) {
                const int col = q0 + nt * 8 + c0;
                if (col     > row_a) sacc[nt][0] = -1e30f;
                if (col + 1 > row_a) sacc[nt][1] = -1e30f;
                if (col     > row_b) sacc[nt][2] = -1e30f;
                if (col + 1 > row_b) sacc[nt][3] = -1e30f;
            }
        }

        float mx0 = -1e30f, mx1 = -1e30f;
#pragma unroll
        for (int nt = 0; nt < 8; nt++) {
            mx0 = fmaxf(mx0, fmaxf(sacc[nt][0], sacc[nt][1]));
            mx1 = fmaxf(mx1, fmaxf(sacc[nt][2], sacc[nt][3]));
        }
        mx0 = fmaxf(mx0, __shfl_xor_sync(0xffffffffu, mx0, 1));
        mx0 = fmaxf(mx0, __shfl_xor_sync(0xffffffffu, mx0, 2));
        mx1 = fmaxf(mx1, __shfl_xor_sync(0xffffffffu, mx1, 1));
        mx1 = fmaxf(mx1, __shfl_xor_sync(0xffffffffu, mx1, 2));
        const float mn0 = fmaxf(m0, mx0), mn1 = fmaxf(m1, mx1);
        const float al0 = ex2((m0 - mn0) * LSCALE);
        const float al1 = ex2((m1 - mn1) * LSCALE);
        m0 = mn0; m1 = mn1;

        float rs0 = 0.f, rs1 = 0.f;
#pragma unroll
        for (int nt = 0; nt < 8; nt++) {
            sacc[nt][0] = ex2((sacc[nt][0] - mn0) * LSCALE);
            sacc[nt][1] = ex2((sacc[nt][1] - mn0) * LSCALE);
            sacc[nt][2] = ex2((sacc[nt][2] - mn1) * LSCALE);
            sacc[nt][3] = ex2((sacc[nt][3] - mn1) * LSCALE);
            rs0 += sacc[nt][0] + sacc[nt][1];
            rs1 += sacc[nt][2] + sacc[nt][3];
        }
        rs0 += __shfl_xor_sync(0xffffffffu, rs0, 1);
        rs0 += __shfl_xor_sync(0xffffffffu, rs0, 2);
        rs1 += __shfl_xor_sync(0xffffffffu, rs1, 1);
        rs1 += __shfl_xor_sync(0xffffffffu, rs1, 2);
        l0 = l0 * al0 + rs0;
        l1 = l1 * al1 + rs1;
#pragma unroll
        for (int nt = 0; nt < 8; nt++) {
            oacc[nt][0] *= al0; oacc[nt][1] *= al0;
            oacc[nt][2] *= al1; oacc[nt][3] *= al1;
        }

        const uint32_t vbase = sb + AKV(s) + 8192;
#pragma unroll
        for (int kb = 0; kb < 4; kb++) {
            uint32_t ph[4], pl[4];
            split_pack2(sacc[2 * kb][0],     sacc[2 * kb][1],     ph[0], pl[0]);
            split_pack2(sacc[2 * kb][2],     sacc[2 * kb][3],     ph[1], pl[1]);
            split_pack2(sacc[2 * kb + 1][0], sacc[2 * kb + 1][1], ph[2], pl[2]);
            split_pack2(sacc[2 * kb + 1][2], sacc[2 * kb + 1][3], ph[3], pl[3]);
#pragma unroll
            for (int dp = 0; dp < 4; dp++) {
                uint32_t vh[4];
                const int kr = kb * 16 + (mi & 1) * 8 + row_in;
                const int cl = dp * 2 + (mi >> 1);
                const uint32_t off = kr * 128 + ((cl ^ (kr & 7)) << 4);
                ldsm_x4_t(vh, vbase + off);
                mma16816(oacc[dp * 2],     ph, &vh[0]);
                mma16816(oacc[dp * 2],     pl, &vh[0]);
                mma16816(oacc[dp * 2 + 1], ph, &vh[2]);
                mma16816(oacc[dp * 2 + 1], pl, &vh[2]);
            }
        }
        __syncthreads();
    }

    const float inv0 = 1.f / l0, inv1 = 1.f / l1;
    const int row_a = b * SEQ + q0 + wq * 16 + r0;
    const int col_b = h * HDIM + c0;
#pragma unroll
    for (int nt = 0; nt < 8; nt++) {
        const size_t oA = (size_t)row_a * D_MODEL + col_b + nt * 8;
        const size_t oB = (size_t)(row_a + 8) * D_MODEL + col_b + nt * 8;
        *(uint32_t*)(y_h + oA) = pack2(oacc[nt][0] * inv0, oacc[nt][1] * inv0);
        *(uint32_t*)(y_h + oB) = pack2(oacc[nt][2] * inv1, oacc[nt][3] * inv1);
    }
}

// ---------------------------------------------------------------------------
extern "C" void kernel_launch(void* const* d_in, const int* in_sizes, int n_in,
                              void* d_out, int out_size)
{
    (void)in_sizes; (void)n_in; (void)out_size;
    const float* x      = (const float*)d_in[0];
    const float* w_qkv  = (const float*)d_in[1];
    const float* w_proj = (const float*)d_in[2];
    float* out = (float*)d_out;

    __half *qkvh, *qkvl, *xh, *yh, *wqh, *wph;
    cudaGetSymbolAddress((void**)&qkvh, g_qkv_hi);
    cudaGetSymbolAddress((void**)&qkvl, g_qkv_lo);
    cudaGetSymbolAddress((void**)&xh, g_x_h);
    cudaGetSymbolAddress((void**)&yh, g_y_h);
    cudaGetSymbolAddress((void**)&wqh, g_wqkv_h);
    cudaGetSymbolAddress((void**)&wph, g_wproj_h);

    cudaFuncSetAttribute(gemm_mma<true>,  cudaFuncAttributeMaxDynamicSharedMemorySize, GEMM_SMEM);
    cudaFuncSetAttribute(gemm_mma<false>, cudaFuncAttributeMaxDynamicSharedMemorySize, GEMM_SMEM);
    cudaFuncSetAttribute(attn_mma_kernel, cudaFuncAttributeMaxDynamicSharedMemorySize, ATTN_SMEM);

    const int nX  = MROWS * D_MODEL / 4;
    const int nWq = QKV_F * D_MODEL / 4;
    const int nWp = D_MODEL * D_MODEL / 4;

    cvt_fp16_kernel<<<(nX + 255) / 256, 256>>>(x, xh, nX);
    cvt_fp16_kernel<<<(nWq + 255) / 256, 256>>>(w_qkv, wqh, nWq);
    cvt_fp16_kernel<<<(nWp + 255) / 256, 256>>>(w_proj, wph, nWp);

    // qkv (hi/lo) = x @ w_qkv^T
    gemm_mma<true><<<dim3(QKV_F / BN, MROWS / BM), 256, GEMM_SMEM>>>(
        xh, wqh, nullptr, qkvh, qkvl, QKV_F, D_MODEL);

    // attention -> y (single fp16)
    attn_mma_kernel<<<dim3(SEQ / 64, NHEADS, BATCH), 128, ATTN_SMEM>>>(qkvh, qkvl, yh);

    // out = y @ w_proj^T (fp32)
    gemm_mma<false><<<dim3(D_MODEL / BN, MROWS / BM), 256, GEMM_SMEM>>>(
        yh, wph, out, nullptr, nullptr, D_MODEL, D_MODEL);
}

// round 10
// speedup vs baseline: 6.4388x; 1.2154x over previous
#include <cuda_runtime.h>
#include <cuda_fp16.h>
#include <cstdint>
#include <math.h>

#define D_MODEL 1024
#define QKV_F   3072
#define NHEADS  16
#define HDIM    64
#define BATCH   4
#define SEQ     2048
#define MROWS   (BATCH * SEQ)   // 8192

// ---------------------------------------------------------------------------
// Scratch (__device__ globals; allocation-free rule)
// ---------------------------------------------------------------------------
__device__ __half g_qkv_h[(size_t)MROWS * QKV_F];
__device__ __half g_x_h[(size_t)MROWS * D_MODEL];
__device__ __half g_y_h[(size_t)MROWS * D_MODEL];
__device__ __half g_wqkv_h[(size_t)QKV_F * D_MODEL];
__device__ __half g_wproj_h[(size_t)D_MODEL * D_MODEL];

// ---------------------------------------------------------------------------
// Helpers (base sm_103 ISA: mma.sync / ldmatrix / cp.async)
// ---------------------------------------------------------------------------
__device__ __forceinline__ uint32_t smem_u32(const void* p) {
    uint32_t a;
    asm("{ .reg .u64 t; cvta.to.shared.u64 t, %1; cvt.u32.u64 %0, t; }" : "=r"(a) : "l"(p));
    return a;
}
__device__ __forceinline__ void ldsm_x4(uint32_t* r, uint32_t addr) {
    asm volatile("ldmatrix.sync.aligned.m8n8.x4.shared.b16 {%0,%1,%2,%3}, [%4];"
        : "=r"(r[0]), "=r"(r[1]), "=r"(r[2]), "=r"(r[3]) : "r"(addr));
}
__device__ __forceinline__ void ldsm_x4_t(uint32_t* r, uint32_t addr) {
    asm volatile("ldmatrix.sync.aligned.m8n8.x4.trans.shared.b16 {%0,%1,%2,%3}, [%4];"
        : "=r"(r[0]), "=r"(r[1]), "=r"(r[2]), "=r"(r[3]) : "r"(addr));
}
// fp16 inputs, fp32 accum
__device__ __forceinline__ void mma16816(float* d, const uint32_t* a, const uint32_t* b) {
    asm volatile("mma.sync.aligned.m16n8k16.row.col.f32.f16.f16.f32 "
        "{%0,%1,%2,%3}, {%4,%5,%6,%7}, {%8,%9}, {%0,%1,%2,%3};"
        : "+f"(d[0]), "+f"(d[1]), "+f"(d[2]), "+f"(d[3])
        : "r"(a[0]), "r"(a[1]), "r"(a[2]), "r"(a[3]), "r"(b[0]), "r"(b[1]));
}
#define CP_ASYNC16(dst, src) \
    asm volatile("cp.async.cg.shared.global [%0], [%1], 16;" :: "r"(dst), "l"(src) : "memory")
#define CP_COMMIT() asm volatile("cp.async.commit_group;" ::: "memory")

__device__ __forceinline__ float ex2(float x) {
    float y; asm("ex2.approx.f32 %0, %1;" : "=f"(y) : "f"(x)); return y;
}
__device__ __forceinline__ uint32_t pack2(float x0, float x1) {
    __half2 H = __halves2half2(__float2half_rn(x0), __float2half_rn(x1));
    return *reinterpret_cast<uint32_t*>(&H);
}

// ---------------------------------------------------------------------------
// fp32 -> fp16 convert
// ---------------------------------------------------------------------------
__global__ void cvt_fp16_kernel(const float* __restrict__ in,
                                __half* __restrict__ hi, int n4)
{
    int i = blockIdx.x * blockDim.x + threadIdx.x;
    if (i >= n4) return;
    float4 v = ((const float4*)in)[i];
    uint32_t* hp = (uint32_t*)(hi + (size_t)i * 4);
    hp[0] = pack2(v.x, v.y);
    hp[1] = pack2(v.z, v.w);
}

// ---------------------------------------------------------------------------
// mma.sync GEMM: C[M,N] = A[M,K] @ W[N,K]^T  (fp16 x1, fp32 accum)
// CTA 128x128, BK=32, 256 threads, warp tile 64x32, 3-stage cp.async.
// HALF_OUT: write fp16 plane; else fp32.
// ---------------------------------------------------------------------------
#define BM 128
#define BN 128
#define BK 32
#define NSTAGE 3
#define TILEB  (BM * BK * 2)
#define STAGEB (2 * TILEB)            // 16 KB
#define GEMM_SMEM (NSTAGE * STAGEB)   // 48 KB

template<bool HALF_OUT>
__global__ __launch_bounds__(256, 2)
void gemm_mma(const __half* __restrict__ A,
              const __half* __restrict__ Wh,
              float* __restrict__ C,
              __half* __restrict__ Ch,
              int N, int K)
{
    extern __shared__ char smem[];
    const uint32_t sbase = smem_u32(smem);
    const int tid  = threadIdx.x;
    const int wid  = tid >> 5;
    const int lane = tid & 31;
    const int wm   = wid & 1;
    const int wn   = wid >> 1;
    const int m0   = blockIdx.y * BM;
    const int n0   = blockIdx.x * BN;

    const int lrow = tid >> 1;
    const int lc0  = (tid & 1) * 2;
    const int lswz = (lrow >> 1) & 3;

    const __half* srcs[2];
    srcs[0] = A  + (size_t)(m0 + lrow) * K;
    srcs[1] = Wh + (size_t)(n0 + lrow) * K;

    auto LOAD = [&](int s, int c) {
#pragma unroll
        for (int a = 0; a < 2; a++) {
#pragma unroll
            for (int j = 0; j < 2; j++) {
                const int cl = lc0 + j;
                const uint32_t dst = sbase + s * STAGEB + a * TILEB
                                   + lrow * 64 + ((cl ^ lswz) << 4);
                CP_ASYNC16(dst, srcs[a] + (size_t)c * BK + cl * 8);
            }
        }
    };

    float acc[4][4][4];
#pragma unroll
    for (int i = 0; i < 4; i++)
#pragma unroll
        for (int j = 0; j < 4; j++)
#pragma unroll
            for (int k = 0; k < 4; k++) acc[i][j][k] = 0.f;

    const int NC = K / BK;
    LOAD(0, 0);
    CP_COMMIT();
    LOAD(1, 1);
    CP_COMMIT();

    const int mi     = lane >> 3;
    const int row_in = lane & 7;
    const int a_rowadd = (mi & 1) * 8;
    const int a_cadd   = mi >> 1;
    const int b_rowadd = (mi >> 1) * 8;
    const int b_cadd   = mi & 1;

    int s = 0;
    for (int c = 0; c < NC; c++) {
        if (c + 2 < NC) {
            LOAD((s + 2 >= NSTAGE) ? s + 2 - NSTAGE : s + 2, c + 2);
            CP_COMMIT();
            asm volatile("cp.async.wait_group 2;" ::: "memory");
        } else if (c + 1 < NC) {
            asm volatile("cp.async.wait_group 1;" ::: "memory");
        } else {
            asm volatile("cp.async.wait_group 0;" ::: "memory");
        }
        __syncthreads();

        const uint32_t st = sbase + s * STAGEB;
#pragma unroll
        for (int ks = 0; ks < 2; ks++) {
            uint32_t ah[4][4], bh[8];
#pragma unroll
            for (int mt = 0; mt < 4; mt++) {
                const int r  = wm * 64 + mt * 16 + a_rowadd + row_in;
                const int cl = ks * 2 + a_cadd;
                const uint32_t off = r * 64 + ((cl ^ ((r >> 1) & 3)) << 4);
                ldsm_x4(ah[mt], st + 0 * TILEB + off);
            }
#pragma unroll
            for (int p = 0; p < 2; p++) {
                const int r  = wn * 32 + p * 16 + b_rowadd + row_in;
                const int cl = ks * 2 + b_cadd;
                const uint32_t off = r * 64 + ((cl ^ ((r >> 1) & 3)) << 4);
                ldsm_x4(&bh[p * 4], st + 1 * TILEB + off);
            }
#pragma unroll
            for (int mt = 0; mt < 4; mt++)
#pragma unroll
                for (int nt = 0; nt < 4; nt++)
                    mma16816(acc[mt][nt], ah[mt], &bh[nt * 2]);
        }
        __syncthreads();
        s = (s + 1 >= NSTAGE) ? 0 : s + 1;
    }

#pragma unroll
    for (int mt = 0; mt < 4; mt++) {
#pragma unroll
        for (int nt = 0; nt < 4; nt++) {
            const int row = m0 + wm * 64 + mt * 16 + (lane >> 2);
            const int col = n0 + wn * 32 + nt * 8 + (lane & 3) * 2;
            if (HALF_OUT) {
                *(uint32_t*)(Ch + (size_t)row * N + col) =
                    pack2(acc[mt][nt][0], acc[mt][nt][1]);
                *(uint32_t*)(Ch + (size_t)(row + 8) * N + col) =
                    pack2(acc[mt][nt][2], acc[mt][nt][3]);
            } else {
                *(float2*)(C + (size_t)row * N + col) =
                    make_float2(acc[mt][nt][0], acc[mt][nt][1]);
                *(float2*)(C + (size_t)(row + 8) * N + col) =
                    make_float2(acc[mt][nt][2], acc[mt][nt][3]);
            }
        }
    }
}

// ---------------------------------------------------------------------------
// Tensor-core flash attention (causal). 64q x 64k tiles, Dh=64, fp16 x1.
// S = Qh*Kh ; O = Ph*Vh  (fp32 accumulators, online softmax in fp32)
// Smem: Q (8KB) + double-buffered {K,V} (2x16KB). 40 KB total.
// ---------------------------------------------------------------------------
#define AQ      0
#define AKV(s)  (8192 + (s) * 16384)   // K at +0, V at +8192
#define ATTN_SMEM 40960

__global__ __launch_bounds__(128)
void attn_mma_kernel(const __half* __restrict__ qkv,
                     __half* __restrict__ y_h)
{
    extern __shared__ char smem[];
    const uint32_t sb = smem_u32(smem);
    const int tid  = threadIdx.x;
    const int wq   = tid >> 5;
    const int lane = tid & 31;
    const int qt   = gridDim.x - 1 - blockIdx.x;
    const int h    = blockIdx.y;
    const int b    = blockIdx.z;
    const int q0   = qt * 64;

    const int lrow = tid >> 1;
    const int lcb  = (tid & 1) * 4;
    const size_t qrow_g = (size_t)(b * SEQ + q0 + lrow) * QKV_F + h * HDIM;

#pragma unroll
    for (int c = 0; c < 4; c++) {
        const int cl = lcb + c;
        const uint32_t so = lrow * 128 + ((cl ^ (lrow & 7)) << 4);
        CP_ASYNC16(sb + AQ + so, qkv + qrow_g + cl * 8);
    }
    auto LOAD_KV = [&](int kt, int s) {
        const size_t krow_g = (size_t)(b * SEQ + kt * 64 + lrow) * QKV_F + D_MODEL + h * HDIM;
        const size_t vrow_g = krow_g + D_MODEL;
        const uint32_t base = sb + AKV(s);
#pragma unroll
        for (int c = 0; c < 4; c++) {
            const int cl = lcb + c;
            const uint32_t so = lrow * 128 + ((cl ^ (lrow & 7)) << 4);
            CP_ASYNC16(base +    0 + so, qkv + krow_g + cl * 8);
            CP_ASYNC16(base + 8192 + so, qkv + vrow_g + cl * 8);
        }
    };

    LOAD_KV(0, 0);
    CP_COMMIT();

    const int mi     = lane >> 3;
    const int row_in = lane & 7;
    const int r0     = lane >> 2;
    const int c0     = (lane & 3) * 2;

    uint32_t qh[4][4];
    float oacc[8][4];
    float m0 = -1e30f, m1 = -1e30f, l0 = 0.f, l1 = 0.f;
#pragma unroll
    for (int i = 0; i < 8; i++)
#pragma unroll
        for (int j = 0; j < 4; j++) oacc[i][j] = 0.f;

    const float LSCALE = 0.18033688f;     // 0.125 * log2(e)

    for (int kt = 0; kt <= qt; kt++) {
        const int s = kt & 1;
        if (kt < qt) {
            LOAD_KV(kt + 1, s ^ 1);
            CP_COMMIT();
            asm volatile("cp.async.wait_group 1;" ::: "memory");
        } else {
            asm volatile("cp.async.wait_group 0;" ::: "memory");
        }
        __syncthreads();

        if (kt == 0) {
#pragma unroll
            for (int ks = 0; ks < 4; ks++) {
                const int r  = wq * 16 + (mi & 1) * 8 + row_in;
                const int cl = ks * 2 + (mi >> 1);
                const uint32_t off = r * 128 + ((cl ^ (r & 7)) << 4);
                ldsm_x4(qh[ks], sb + AQ + off);
            }
        }

        float sacc[8][4];
#pragma unroll
        for (int i = 0; i < 8; i++)
#pragma unroll
            for (int j = 0; j < 4; j++) sacc[i][j] = 0.f;

        const uint32_t kbase = sb + AKV(s);
#pragma unroll
        for (int ks = 0; ks < 4; ks++) {
#pragma unroll
            for (int ntp = 0; ntp < 4; ntp++) {
                uint32_t kh[4];
                const int r  = ntp * 16 + (mi >> 1) * 8 + row_in;
                const int cl = ks * 2 + (mi & 1);
                const uint32_t off = r * 128 + ((cl ^ (r & 7)) << 4);
                ldsm_x4(kh, kbase + off);
                mma16816(sacc[ntp * 2],     qh[ks], &kh[0]);
                mma16816(sacc[ntp * 2 + 1], qh[ks], &kh[2]);
            }
        }

        if (kt == qt) {
            const int row_a = q0 + wq * 16 + r0;
            const int row_b = row_a + 8;
#pragma unroll
            for (int nt = 0; nt < 8; nt++) {
                const int col = q0 + nt * 8 + c0;
                if (col     > row_a) sacc[nt][0] = -1e30f;
                if (col + 1 > row_a) sacc[nt][1] = -1e30f;
                if (col     > row_b) sacc[nt][2] = -1e30f;
                if (col + 1 > row_b) sacc[nt][3] = -1e30f;
            }
        }

        float mx0 = -1e30f, mx1 = -1e30f;
#pragma unroll
        for (int nt = 0; nt < 8; nt++) {
            mx0 = fmaxf(mx0, fmaxf(sacc[nt][0], sacc[nt][1]));
            mx1 = fmaxf(mx1, fmaxf(sacc[nt][2], sacc[nt][3]));
        }
        mx0 = fmaxf(mx0, __shfl_xor_sync(0xffffffffu, mx0, 1));
        mx0 = fmaxf(mx0, __shfl_xor_sync(0xffffffffu, mx0, 2));
        mx1 = fmaxf(mx1, __shfl_xor_sync(0xffffffffu, mx1, 1));
        mx1 = fmaxf(mx1, __shfl_xor_sync(0xffffffffu, mx1, 2));
        const float mn0 = fmaxf(m0, mx0), mn1 = fmaxf(m1, mx1);
        const float al0 = ex2((m0 - mn0) * LSCALE);
        const float al1 = ex2((m1 - mn1) * LSCALE);
        m0 = mn0; m1 = mn1;

        float rs0 = 0.f, rs1 = 0.f;
#pragma unroll
        for (int nt = 0; nt < 8; nt++) {
            sacc[nt][0] = ex2((sacc[nt][0] - mn0) * LSCALE);
            sacc[nt][1] = ex2((sacc[nt][1] - mn0) * LSCALE);
            sacc[nt][2] = ex2((sacc[nt][2] - mn1) * LSCALE);
            sacc[nt][3] = ex2((sacc[nt][3] - mn1) * LSCALE);
            rs0 += sacc[nt][0] + sacc[nt][1];
            rs1 += sacc[nt][2] + sacc[nt][3];
        }
        rs0 += __shfl_xor_sync(0xffffffffu, rs0, 1);
        rs0 += __shfl_xor_sync(0xffffffffu, rs0, 2);
        rs1 += __shfl_xor_sync(0xffffffffu, rs1, 1);
        rs1 += __shfl_xor_sync(0xffffffffu, rs1, 2);
        l0 = l0 * al0 + rs0;
        l1 = l1 * al1 + rs1;
#pragma unroll
        for (int nt = 0; nt < 8; nt++) {
            oacc[nt][0] *= al0; oacc[nt][1] *= al0;
            oacc[nt][2] *= al1; oacc[nt][3] *= al1;
        }

        const uint32_t vbase = sb + AKV(s) + 8192;
#pragma unroll
        for (int kb = 0; kb < 4; kb++) {
            uint32_t ph[4];
            ph[0] = pack2(sacc[2 * kb][0],     sacc[2 * kb][1]);
            ph[1] = pack2(sacc[2 * kb][2],     sacc[2 * kb][3]);
            ph[2] = pack2(sacc[2 * kb + 1][0], sacc[2 * kb + 1][1]);
            ph[3] = pack2(sacc[2 * kb + 1][2], sacc[2 * kb + 1][3]);
#pragma unroll
            for (int dp = 0; dp < 4; dp++) {
                uint32_t vh[4];
                const int kr = kb * 16 + (mi & 1) * 8 + row_in;
                const int cl = dp * 2 + (mi >> 1);
                const uint32_t off = kr * 128 + ((cl ^ (kr & 7)) << 4);
                ldsm_x4_t(vh, vbase + off);
                mma16816(oacc[dp * 2],     ph, &vh[0]);
                mma16816(oacc[dp * 2 + 1], ph, &vh[2]);
            }
        }
        __syncthreads();
    }

    const float inv0 = 1.f / l0, inv1 = 1.f / l1;
    const int row_a = b * SEQ + q0 + wq * 16 + r0;
    const int col_b = h * HDIM + c0;
#pragma unroll
    for (int nt = 0; nt < 8; nt++) {
        const size_t oA = (size_t)row_a * D_MODEL + col_b + nt * 8;
        const size_t oB = (size_t)(row_a + 8) * D_MODEL + col_b + nt * 8;
        *(uint32_t*)(y_h + oA) = pack2(oacc[nt][0] * inv0, oacc[nt][1] * inv0);
        *(uint32_t*)(y_h + oB) = pack2(oacc[nt][2] * inv1, oacc[nt][3] * inv1);
    }
}

// ---------------------------------------------------------------------------
extern "C" void kernel_launch(void* const* d_in, const int* in_sizes, int n_in,
                              void* d_out, int out_size)
{
    (void)in_sizes; (void)n_in; (void)out_size;
    const float* x      = (const float*)d_in[0];
    const float* w_qkv  = (const float*)d_in[1];
    const float* w_proj = (const float*)d_in[2];
    float* out = (float*)d_out;

    __half *qkvh, *xh, *yh, *wqh, *wph;
    cudaGetSymbolAddress((void**)&qkvh, g_qkv_h);
    cudaGetSymbolAddress((void**)&xh, g_x_h);
    cudaGetSymbolAddress((void**)&yh, g_y_h);
    cudaGetSymbolAddress((void**)&wqh, g_wqkv_h);
    cudaGetSymbolAddress((void**)&wph, g_wproj_h);

    cudaFuncSetAttribute(gemm_mma<true>,  cudaFuncAttributeMaxDynamicSharedMemorySize, GEMM_SMEM);
    cudaFuncSetAttribute(gemm_mma<false>, cudaFuncAttributeMaxDynamicSharedMemorySize, GEMM_SMEM);
    cudaFuncSetAttribute(attn_mma_kernel, cudaFuncAttributeMaxDynamicSharedMemorySize, ATTN_SMEM);

    const int nX  = MROWS * D_MODEL / 4;
    const int nWq = QKV_F * D_MODEL / 4;
    const int nWp = D_MODEL * D_MODEL / 4;

    cvt_fp16_kernel<<<(nX + 255) / 256, 256>>>(x, xh, nX);
    cvt_fp16_kernel<<<(nWq + 255) / 256, 256>>>(w_qkv, wqh, nWq);
    cvt_fp16_kernel<<<(nWp + 255) / 256, 256>>>(w_proj, wph, nWp);

    // qkv (fp16) = x @ w_qkv^T
    gemm_mma<true><<<dim3(QKV_F / BN, MROWS / BM), 256, GEMM_SMEM>>>(
        xh, wqh, nullptr, qkvh, QKV_F, D_MODEL);

    // attention -> y (fp16)
    attn_mma_kernel<<<dim3(SEQ / 64, NHEADS, BATCH), 128, ATTN_SMEM>>>(qkvh, yh);

    // out = y @ w_proj^T (fp32)
    gemm_mma<false><<<dim3(D_MODEL / BN, MROWS / BM), 256, GEMM_SMEM>>>(
        yh, wph, out, nullptr, D_MODEL, D_MODEL);
}